// round 1
// baseline (speedup 1.0000x reference)
#include <cuda_runtime.h>
#include <cstdint>
#include <math.h>

#define BATCH  4
#define SEQ    2048
#define DMODEL 1024
#define NHEADS 16
#define DHEAD  64
#define NBH    (BATCH * NHEADS)   // 64

// Scratch (static __device__ arrays: allocation-free per harness rules)
// Q, K stored d-major per head: [bh][d][s]  (so attention needs no smem transpose)
// V stored s-major:             [bh][s][d]
__device__ float g_Q[(size_t)NBH * DHEAD * SEQ];
__device__ float g_K[(size_t)NBH * DHEAD * SEQ];
__device__ float g_V[(size_t)NBH * SEQ * DHEAD];

// ---------------------------------------------------------------------------
// Fused QKV projection: C = X[8192,1024] @ W[1024,1024], blockIdx.z picks W.
// 128x128 block tile, K-chunk 8, 8x8 per thread, register prefetch.
// ---------------------------------------------------------------------------
__global__ __launch_bounds__(256, 2)
void qkv_proj_kernel(const float* __restrict__ X,
                     const float* __restrict__ Wq,
                     const float* __restrict__ Wk,
                     const float* __restrict__ Wv)
{
    constexpr int BM = 128, BN = 128, BK = 8;
    __shared__ float Ash[BK][BM + 4];   // [k][m]
    __shared__ float Bsh[BK][BN + 4];   // [k][n]

    const int which = blockIdx.z;
    const float* __restrict__ W = (which == 0) ? Wq : (which == 1) ? Wk : Wv;
    float* __restrict__ outp = (which == 0) ? g_Q : (which == 1) ? g_K : g_V;

    const int tid = threadIdx.x;
    const int tx = tid & 15, ty = tid >> 4;
    const int m0 = blockIdx.y * BM;
    const int n0 = blockIdx.x * BN;

    // global load mappings
    const int aRow = tid >> 1,  aCol = (tid & 1) << 2;    // 128 x 8 tile of X
    const int bRow = tid >> 5,  bCol = (tid & 31) << 2;   // 8 x 128 tile of W

    const float* Aptr = X + (size_t)(m0 + aRow) * DMODEL + aCol;
    const float* Bptr = W + (size_t)bRow * DMODEL + n0 + bCol;

    float4 aReg = *(const float4*)Aptr;
    float4 bReg = *(const float4*)Bptr;

    float acc[8][8];
#pragma unroll
    for (int i = 0; i < 8; i++)
#pragma unroll
        for (int j = 0; j < 8; j++) acc[i][j] = 0.f;

    const int nChunks = DMODEL / BK;   // 128
    for (int ch = 0; ch < nChunks; ch++) {
        // commit prefetched tile to shared (A transposed to [k][m])
        Ash[aCol + 0][aRow] = aReg.x;
        Ash[aCol + 1][aRow] = aReg.y;
        Ash[aCol + 2][aRow] = aReg.z;
        Ash[aCol + 3][aRow] = aReg.w;
        *(float4*)&Bsh[bRow][bCol] = bReg;
        __syncthreads();

        if (ch + 1 < nChunks) {   // prefetch next chunk (overlaps with compute)
            aReg = *(const float4*)(Aptr + (ch + 1) * BK);
            bReg = *(const float4*)(Bptr + (size_t)(ch + 1) * BK * DMODEL);
        }

#pragma unroll
        for (int k = 0; k < BK; k++) {
            float4 a0 = *(const float4*)&Ash[k][ty * 8];
            float4 a1 = *(const float4*)&Ash[k][ty * 8 + 4];
            float4 b0 = *(const float4*)&Bsh[k][tx * 8];
            float4 b1 = *(const float4*)&Bsh[k][tx * 8 + 4];
            float a[8] = {a0.x, a0.y, a0.z, a0.w, a1.x, a1.y, a1.z, a1.w};
            float b[8] = {b0.x, b0.y, b0.z, b0.w, b1.x, b1.y, b1.z, b1.w};
#pragma unroll
            for (int i = 0; i < 8; i++)
#pragma unroll
                for (int j = 0; j < 8; j++)
                    acc[i][j] = fmaf(a[i], b[j], acc[i][j]);
        }
        __syncthreads();
    }

    // Epilogue. m -> (batch b, seq s); n -> (head h, dim d).
    const int bb = m0 / SEQ;                    // BM=128 divides SEQ, so constant per block
    const int sBase = (m0 % SEQ) + ty * 8;

    if (which < 2) {
        // transposed: out[((b*H + h)*DHEAD + d)*SEQ + s]
#pragma unroll
        for (int j = 0; j < 8; j++) {
            int n = n0 + tx * 8 + j;
            int h = n >> 6, d = n & 63;
            size_t base = ((size_t)(bb * NHEADS + h) * DHEAD + d) * SEQ + sBase;
            *(float4*)(outp + base)     = make_float4(acc[0][j], acc[1][j], acc[2][j], acc[3][j]);
            *(float4*)(outp + base + 4) = make_float4(acc[4][j], acc[5][j], acc[6][j], acc[7][j]);
        }
    } else {
        // normal: out[((b*H + h)*SEQ + s)*DHEAD + d]   (h constant across j: n0+tx*8 ≡ 0 mod 8, 8 cols within one head)
#pragma unroll
        for (int i = 0; i < 8; i++) {
            int n = n0 + tx * 8;
            int h = n >> 6, d = n & 63;
            size_t base = ((size_t)(bb * NHEADS + h) * SEQ + sBase + i) * DHEAD + d;
            *(float4*)(outp + base)     = make_float4(acc[i][0], acc[i][1], acc[i][2], acc[i][3]);
            *(float4*)(outp + base + 4) = make_float4(acc[i][4], acc[i][5], acc[i][6], acc[i][7]);
        }
    }
}

// ---------------------------------------------------------------------------
// Flash attention: per block 128 queries x (64-key tiles), online softmax.
// Mask: tril(ones, k=1)  =>  key valid iff k <= q+1.
// ---------------------------------------------------------------------------
constexpr int BR = 128;
constexpr int QS = BR + 4;   // 132 (padded row stride, floats)
constexpr int CS = 64 + 4;   // 68
constexpr int ATTN_SMEM = (64 * QS + 64 * CS + 64 * CS + 64 * QS) * 4;  // 102400 B

__global__ __launch_bounds__(256, 1)
void attn_kernel(float* __restrict__ out)
{
    extern __shared__ float sm[];
    float* Qsh = sm;                 // [d][r]  64 x 132
    float* Ksh = Qsh + 64 * QS;      // [d][c]  64 x 68
    float* Vsh = Ksh + 64 * CS;      // [k][d]  64 x 68
    float* Psh = Vsh + 64 * CS;      // [k][r]  64 x 132

    const int tid = threadIdx.x;
    const int tx = tid & 15, ty = tid >> 4;
    const int bh = blockIdx.y;
    const int qt = (gridDim.x - 1) - blockIdx.x;   // heavy (large-qt) blocks first
    const int q0 = qt * BR;

    const float* Qg = g_Q + (size_t)bh * DHEAD * SEQ;
    const float* Kg = g_K + (size_t)bh * DHEAD * SEQ;
    const float* Vg = g_V + (size_t)bh * SEQ * DHEAD;

    // load Q tile [d][r]  (64 x 128 floats)
#pragma unroll
    for (int it = 0; it < 8; it++) {
        int idx = tid + it * 256;
        int d = idx >> 5;
        int r4 = (idx & 31) << 2;
        *(float4*)&Qsh[d * QS + r4] = *(const float4*)(Qg + (size_t)d * SEQ + q0 + r4);
    }

    float O[8][4];
    float mrow[8], lrow[8];
#pragma unroll
    for (int i = 0; i < 8; i++) {
        mrow[i] = -INFINITY; lrow[i] = 0.f;
#pragma unroll
        for (int j = 0; j < 4; j++) O[i][j] = 0.f;
    }

    // max needed key = q0+127+1 -> tile index 2*qt+2
    const int ktmax = min(2 * qt + 2, SEQ / 64 - 1);

    for (int kt = 0; kt <= ktmax; kt++) {
        // load K [d][c] and V [k][d] tiles (64 x 64 each)
#pragma unroll
        for (int it = 0; it < 4; it++) {
            int idx = tid + it * 256;
            int row = idx >> 4;
            int c4 = (idx & 15) << 2;
            *(float4*)&Ksh[row * CS + c4] = *(const float4*)(Kg + (size_t)row * SEQ + kt * 64 + c4);
            *(float4*)&Vsh[row * CS + c4] = *(const float4*)(Vg + (size_t)(kt * 64 + row) * DHEAD + c4);
        }
        __syncthreads();

        // S = Q @ K^T  (thread tile: 8 rows x 4 key-cols)
        float s[8][4];
#pragma unroll
        for (int i = 0; i < 8; i++)
#pragma unroll
            for (int j = 0; j < 4; j++) s[i][j] = 0.f;

#pragma unroll 8
        for (int d = 0; d < 64; d++) {
            float4 a0 = *(const float4*)&Qsh[d * QS + ty * 8];
            float4 a1 = *(const float4*)&Qsh[d * QS + ty * 8 + 4];
            float4 b  = *(const float4*)&Ksh[d * CS + tx * 4];
            float a[8]  = {a0.x, a0.y, a0.z, a0.w, a1.x, a1.y, a1.z, a1.w};
            float bv[4] = {b.x, b.y, b.z, b.w};
#pragma unroll
            for (int i = 0; i < 8; i++)
#pragma unroll
                for (int j = 0; j < 4; j++)
                    s[i][j] = fmaf(a[i], bv[j], s[i][j]);
        }

        // scale + mask + online softmax (rows reduced over 16-lane groups)
        const bool maskedTile = (kt >= 2 * qt);
#pragma unroll
        for (int i = 0; i < 8; i++) {
            const int qg = q0 + ty * 8 + i;
            float tmax = -INFINITY;
#pragma unroll
            for (int j = 0; j < 4; j++) {
                float v = s[i][j] * 0.125f;   // 1/sqrt(64); mask stays -inf either way
                if (maskedTile && (kt * 64 + tx * 4 + j > qg + 1)) v = -INFINITY;
                s[i][j] = v;
                tmax = fmaxf(tmax, v);
            }
            tmax = fmaxf(tmax, __shfl_xor_sync(0xffffffffu, tmax, 8));
            tmax = fmaxf(tmax, __shfl_xor_sync(0xffffffffu, tmax, 4));
            tmax = fmaxf(tmax, __shfl_xor_sync(0xffffffffu, tmax, 2));
            tmax = fmaxf(tmax, __shfl_xor_sync(0xffffffffu, tmax, 1));

            float mn = fmaxf(mrow[i], tmax);
            float sum = 0.f;
#pragma unroll
            for (int j = 0; j < 4; j++) {
                float p = __expf(s[i][j] - mn);   // -inf -> 0
                s[i][j] = p;
                sum += p;
            }
            sum += __shfl_xor_sync(0xffffffffu, sum, 8);
            sum += __shfl_xor_sync(0xffffffffu, sum, 4);
            sum += __shfl_xor_sync(0xffffffffu, sum, 2);
            sum += __shfl_xor_sync(0xffffffffu, sum, 1);

            float sc = __expf(mrow[i] - mn);      // first iter: exp(-inf)=0
            lrow[i] = lrow[i] * sc + sum;
            mrow[i] = mn;
#pragma unroll
            for (int j = 0; j < 4; j++) O[i][j] *= sc;

            // store P transposed: Psh[k][r]
#pragma unroll
            for (int j = 0; j < 4; j++)
                Psh[(tx * 4 + j) * QS + ty * 8 + i] = s[i][j];
        }
        __syncthreads();

        // O += P @ V  (same 8x4 thread tile, cols now head-dims)
#pragma unroll 8
        for (int k = 0; k < 64; k++) {
            float4 a0 = *(const float4*)&Psh[k * QS + ty * 8];
            float4 a1 = *(const float4*)&Psh[k * QS + ty * 8 + 4];
            float4 b  = *(const float4*)&Vsh[k * CS + tx * 4];
            float a[8]  = {a0.x, a0.y, a0.z, a0.w, a1.x, a1.y, a1.z, a1.w};
            float bv[4] = {b.x, b.y, b.z, b.w};
#pragma unroll
            for (int i = 0; i < 8; i++)
#pragma unroll
                for (int j = 0; j < 4; j++)
                    O[i][j] = fmaf(a[i], bv[j], O[i][j]);
        }
        __syncthreads();
    }

    // epilogue: out[b][s][h*64 + d]
    const int bb = bh >> 4, h = bh & 15;
#pragma unroll
    for (int i = 0; i < 8; i++) {
        float inv = 1.f / lrow[i];
        size_t idx = ((size_t)(bb * SEQ + q0 + ty * 8 + i)) * DMODEL + h * DHEAD + tx * 4;
        *(float4*)(out + idx) = make_float4(O[i][0] * inv, O[i][1] * inv,
                                            O[i][2] * inv, O[i][3] * inv);
    }
}

// ---------------------------------------------------------------------------
extern "C" void kernel_launch(void* const* d_in, const int* in_sizes, int n_in,
                              void* d_out, int out_size)
{
    const float* X  = (const float*)d_in[0];
    const float* Wq = (const float*)d_in[1];
    const float* Wk = (const float*)d_in[2];
    const float* Wv = (const float*)d_in[3];
    float* out = (float*)d_out;

    cudaFuncSetAttribute(attn_kernel,
                         cudaFuncAttributeMaxDynamicSharedMemorySize, ATTN_SMEM);

    dim3 pgrid(DMODEL / 128, (BATCH * SEQ) / 128, 3);   // 8 x 64 x 3
    qkv_proj_kernel<<<pgrid, 256>>>(X, Wq, Wk, Wv);

    dim3 agrid(SEQ / BR, NBH);                          // 16 x 64
    attn_kernel<<<agrid, 256, ATTN_SMEM>>>(out);
}

// round 4
// speedup vs baseline: 1.4037x; 1.4037x over previous
#include <cuda_runtime.h>
#include <cuda_fp16.h>
#include <cstdint>
#include <math.h>

#define BATCH  4
#define SEQ    2048
#define DMODEL 1024
#define NHEADS 16
#define DHEAD  64
#define NBH    (BATCH * NHEADS)   // 64
#define MTOT   (BATCH * SEQ)      // 8192

// ---------------- scratch (static device arrays; allocation-free) ----------
__device__ float g_Q[(size_t)NBH * DHEAD * SEQ];   // [bh][d][s]
__device__ float g_K[(size_t)NBH * DHEAD * SEQ];   // [bh][d][s]
__device__ float g_V[(size_t)NBH * SEQ * DHEAD];   // [bh][s][d]

__device__ __half g_Xhi[(size_t)MTOT * DMODEL];
__device__ __half g_Xlo[(size_t)MTOT * DMODEL];
__device__ __half g_WThi[(size_t)3 * DMODEL * DMODEL];  // [which][n][k]
__device__ __half g_WTlo[(size_t)3 * DMODEL * DMODEL];

// ---------------- helpers ---------------------------------------------------
__device__ __forceinline__ void cp16(uint32_t dst, const void* src) {
    asm volatile("cp.async.cg.shared.global [%0], [%1], 16;" :: "r"(dst), "l"(src));
}
#define CP_COMMIT() asm volatile("cp.async.commit_group;" ::: "memory")
#define CP_WAIT(n)  asm volatile("cp.async.wait_group %0;" :: "n"(n) : "memory")

__device__ __forceinline__ uint32_t smem_u32(const void* p) {
    uint32_t a;
    asm("{ .reg .u64 t; cvta.to.shared.u64 t, %1; cvt.u32.u64 %0, t; }" : "=r"(a) : "l"(p));
    return a;
}
__device__ __forceinline__ uint32_t ld32sh(const __half* p) {
    return *(const uint32_t*)p;
}
__device__ __forceinline__ void mma16816(float* c, const uint32_t* a, const uint32_t* b) {
    asm volatile("mma.sync.aligned.m16n8k16.row.col.f32.f16.f16.f32 "
                 "{%0,%1,%2,%3}, {%4,%5,%6,%7}, {%8,%9}, {%0,%1,%2,%3};"
                 : "+f"(c[0]), "+f"(c[1]), "+f"(c[2]), "+f"(c[3])
                 : "r"(a[0]), "r"(a[1]), "r"(a[2]), "r"(a[3]), "r"(b[0]), "r"(b[1]));
}

// ---------------- conversion kernels ---------------------------------------
__global__ void split_x_kernel(const float* __restrict__ X)
{
    size_t i = ((size_t)blockIdx.x * blockDim.x + threadIdx.x) * 4;
    float4 v = *(const float4*)(X + i);
    float f[4] = {v.x, v.y, v.z, v.w};
#pragma unroll
    for (int j = 0; j < 4; j++) {
        __half hi = __float2half_rn(f[j]);
        g_Xhi[i + j] = hi;
        g_Xlo[i + j] = __float2half_rn(f[j] - __half2float(hi));
    }
}

// W[k][n] -> WT[which][n][k], split hi/lo
__global__ void split_wt_kernel(const float* __restrict__ Wq,
                                const float* __restrict__ Wk,
                                const float* __restrict__ Wv)
{
    __shared__ float t[32][33];
    const float* W = (blockIdx.z == 0) ? Wq : (blockIdx.z == 1) ? Wk : Wv;
    int tx = threadIdx.x, ty = threadIdx.y;
    int n = blockIdx.x * 32 + tx;
#pragma unroll
    for (int i = 0; i < 4; i++) {
        int k = blockIdx.y * 32 + ty + i * 8;
        t[ty + i * 8][tx] = W[(size_t)k * DMODEL + n];
    }
    __syncthreads();
    size_t base = (size_t)blockIdx.z * DMODEL * DMODEL;
#pragma unroll
    for (int i = 0; i < 4; i++) {
        int nn = blockIdx.x * 32 + ty + i * 8;
        int kk = blockIdx.y * 32 + tx;
        float f = t[tx][ty + i * 8];
        __half hi = __float2half_rn(f);
        g_WThi[base + (size_t)nn * DMODEL + kk] = hi;
        g_WTlo[base + (size_t)nn * DMODEL + kk] = __float2half_rn(f - __half2float(hi));
    }
}

// ---------------- mma.sync split-fp16 projection GEMM ----------------------
// C[128 x 128] per CTA = X @ WT^T. 8 warps, warp tile 64x32. K chunks of 32.
constexpr int GKC = 32;                    // k per chunk
constexpr int NCHUNK = DMODEL / GKC;       // 32
constexpr int SST = 40;                    // smem row stride in halfs (32 + 8 pad)
constexpr uint32_t AHI = 0;
constexpr uint32_t ALO = 128 * SST * 2;            // 10240
constexpr uint32_t BHI = 2 * 128 * SST * 2;        // 20480
constexpr uint32_t BLO = 3 * 128 * SST * 2;        // 30720
constexpr uint32_t STAGE = 4 * 128 * SST * 2;      // 40960
constexpr uint32_t GEMM_SMEM = 2 * STAGE;          // 81920

__global__ __launch_bounds__(256, 2)
void qkv_mma_kernel()
{
    extern __shared__ uint8_t sm[];
    const uint32_t sb = smem_u32(sm);

    const int tid = threadIdx.x;
    const int lane = tid & 31;
    const int warp = tid >> 5;
    const int wy = warp >> 2;            // 0..1 -> m offset 64*wy
    const int wx = warp & 3;             // 0..3 -> n offset 32*wx
    const int gid = lane >> 2;           // 0..7
    const int tig = lane & 3;            // 0..3

    const int which = blockIdx.z;
    const int n0 = blockIdx.x * 128;
    const int m0 = blockIdx.y * 128;

    const __half* __restrict__ WThi = g_WThi + (size_t)which * DMODEL * DMODEL;
    const __half* __restrict__ WTlo = g_WTlo + (size_t)which * DMODEL * DMODEL;

    // ---- chunk loader: 8 cp16 per thread ---------------------------------
    auto load_chunk = [&](int c, int s) {
        const uint32_t stage = sb + (uint32_t)s * STAGE;
        const int c0 = c * GKC;
#pragma unroll
        for (int it = 0; it < 2; it++) {
            int idx = tid + it * 256;          // 0..511
            int r = idx >> 2, kg = idx & 3;
            uint32_t doff = (uint32_t)(r * SST * 2 + kg * 16);
            size_t asrc = (size_t)(m0 + r) * DMODEL + c0 + kg * 8;
            size_t bsrc = (size_t)(n0 + r) * DMODEL + c0 + kg * 8;
            cp16(stage + AHI + doff, g_Xhi + asrc);
            cp16(stage + ALO + doff, g_Xlo + asrc);
            cp16(stage + BHI + doff, WThi + bsrc);
            cp16(stage + BLO + doff, WTlo + bsrc);
        }
    };

    float acc[4][4][4];
#pragma unroll
    for (int mt = 0; mt < 4; mt++)
#pragma unroll
        for (int nt = 0; nt < 4; nt++)
#pragma unroll
            for (int j = 0; j < 4; j++) acc[mt][nt][j] = 0.f;

    load_chunk(0, 0);
    CP_COMMIT();

    for (int c = 0; c < NCHUNK; c++) {
        const int s = c & 1;
        if (c + 1 < NCHUNK) {
            load_chunk(c + 1, s ^ 1);
            CP_COMMIT();
            CP_WAIT(1);
        } else {
            CP_WAIT(0);
        }
        __syncthreads();

        const __half* Ah = (const __half*)(sm + s * STAGE + AHI);
        const __half* Al = (const __half*)(sm + s * STAGE + ALO);
        const __half* Bh = (const __half*)(sm + s * STAGE + BHI);
        const __half* Bl = (const __half*)(sm + s * STAGE + BLO);

#pragma unroll
        for (int ks = 0; ks < 2; ks++) {
            const int kbase = ks * 16 + tig * 2;
            uint32_t bh[4][2], bl[4][2];
#pragma unroll
            for (int nt = 0; nt < 4; nt++) {
                int rb = (wx * 32 + nt * 8 + gid) * SST + kbase;
                bh[nt][0] = ld32sh(Bh + rb);
                bh[nt][1] = ld32sh(Bh + rb + 8);
                bl[nt][0] = ld32sh(Bl + rb);
                bl[nt][1] = ld32sh(Bl + rb + 8);
            }
#pragma unroll
            for (int mt = 0; mt < 4; mt++) {
                int ra = (wy * 64 + mt * 16 + gid) * SST + kbase;
                uint32_t ah[4], al[4];
                ah[0] = ld32sh(Ah + ra);
                ah[1] = ld32sh(Ah + ra + 8 * SST);
                ah[2] = ld32sh(Ah + ra + 8);
                ah[3] = ld32sh(Ah + ra + 8 * SST + 8);
                al[0] = ld32sh(Al + ra);
                al[1] = ld32sh(Al + ra + 8 * SST);
                al[2] = ld32sh(Al + ra + 8);
                al[3] = ld32sh(Al + ra + 8 * SST + 8);
#pragma unroll
                for (int nt = 0; nt < 4; nt++) {
                    mma16816(acc[mt][nt], ah, bh[nt]);
                    mma16816(acc[mt][nt], ah, bl[nt]);
                    mma16816(acc[mt][nt], al, bh[nt]);
                }
            }
        }
        __syncthreads();
    }

    // ---- epilogue ---------------------------------------------------------
#pragma unroll
    for (int mt = 0; mt < 4; mt++) {
#pragma unroll
        for (int half_row = 0; half_row < 2; half_row++) {
            const int m = m0 + wy * 64 + mt * 16 + gid + half_row * 8;
            const int bb = m >> 11;
            const int sIdx = m & 2047;
#pragma unroll
            for (int nt = 0; nt < 4; nt++) {
                const int n = n0 + wx * 32 + nt * 8 + tig * 2;
                const int h = n >> 6, d = n & 63;
                const float v0 = acc[mt][nt][half_row * 2 + 0];
                const float v1 = acc[mt][nt][half_row * 2 + 1];
                if (which < 2) {
                    float* outp = (which == 0) ? g_Q : g_K;
                    size_t base = ((size_t)(bb * NHEADS + h) * DHEAD + d) * SEQ + sIdx;
                    outp[base] = v0;
                    outp[base + SEQ] = v1;           // d+1 row
                } else {
                    size_t idx = ((size_t)(bb * NHEADS + h) * SEQ + sIdx) * DHEAD + d;
                    *(float2*)(g_V + idx) = make_float2(v0, v1);
                }
            }
        }
    }
}

// ---------------------------------------------------------------------------
// Flash attention (unchanged): fp32 FFMA, online softmax.
// ---------------------------------------------------------------------------
constexpr int BR = 128;
constexpr int QS = BR + 4;
constexpr int CS = 64 + 4;
constexpr int ATTN_SMEM = (64 * QS + 64 * CS + 64 * CS + 64 * QS) * 4;

__global__ __launch_bounds__(256, 1)
void attn_kernel(float* __restrict__ out)
{
    extern __shared__ float smf[];
    float* Qsh = smf;
    float* Ksh = Qsh + 64 * QS;
    float* Vsh = Ksh + 64 * CS;
    float* Psh = Vsh + 64 * CS;

    const int tid = threadIdx.x;
    const int tx = tid & 15, ty = tid >> 4;
    const int bh = blockIdx.y;
    const int qt = (gridDim.x - 1) - blockIdx.x;
    const int q0 = qt * BR;

    const float* Qg = g_Q + (size_t)bh * DHEAD * SEQ;
    const float* Kg = g_K + (size_t)bh * DHEAD * SEQ;
    const float* Vg = g_V + (size_t)bh * SEQ * DHEAD;

#pragma unroll
    for (int it = 0; it < 8; it++) {
        int idx = tid + it * 256;
        int d = idx >> 5;
        int r4 = (idx & 31) << 2;
        *(float4*)&Qsh[d * QS + r4] = *(const float4*)(Qg + (size_t)d * SEQ + q0 + r4);
    }

    float O[8][4];
    float mrow[8], lrow[8];
#pragma unroll
    for (int i = 0; i < 8; i++) {
        mrow[i] = -INFINITY; lrow[i] = 0.f;
#pragma unroll
        for (int j = 0; j < 4; j++) O[i][j] = 0.f;
    }

    const int ktmax = min(2 * qt + 2, SEQ / 64 - 1);

    for (int kt = 0; kt <= ktmax; kt++) {
#pragma unroll
        for (int it = 0; it < 4; it++) {
            int idx = tid + it * 256;
            int row = idx >> 4;
            int c4 = (idx & 15) << 2;
            *(float4*)&Ksh[row * CS + c4] = *(const float4*)(Kg + (size_t)row * SEQ + kt * 64 + c4);
            *(float4*)&Vsh[row * CS + c4] = *(const float4*)(Vg + (size_t)(kt * 64 + row) * DHEAD + c4);
        }
        __syncthreads();

        float s[8][4];
#pragma unroll
        for (int i = 0; i < 8; i++)
#pragma unroll
            for (int j = 0; j < 4; j++) s[i][j] = 0.f;

#pragma unroll 8
        for (int d = 0; d < 64; d++) {
            float4 a0 = *(const float4*)&Qsh[d * QS + ty * 8];
            float4 a1 = *(const float4*)&Qsh[d * QS + ty * 8 + 4];
            float4 b  = *(const float4*)&Ksh[d * CS + tx * 4];
            float a[8]  = {a0.x, a0.y, a0.z, a0.w, a1.x, a1.y, a1.z, a1.w};
            float bv[4] = {b.x, b.y, b.z, b.w};
#pragma unroll
            for (int i = 0; i < 8; i++)
#pragma unroll
                for (int j = 0; j < 4; j++)
                    s[i][j] = fmaf(a[i], bv[j], s[i][j]);
        }

        const bool maskedTile = (kt >= 2 * qt);
#pragma unroll
        for (int i = 0; i < 8; i++) {
            const int qg = q0 + ty * 8 + i;
            float tmax = -INFINITY;
#pragma unroll
            for (int j = 0; j < 4; j++) {
                float v = s[i][j] * 0.125f;
                if (maskedTile && (kt * 64 + tx * 4 + j > qg + 1)) v = -INFINITY;
                s[i][j] = v;
                tmax = fmaxf(tmax, v);
            }
            tmax = fmaxf(tmax, __shfl_xor_sync(0xffffffffu, tmax, 8));
            tmax = fmaxf(tmax, __shfl_xor_sync(0xffffffffu, tmax, 4));
            tmax = fmaxf(tmax, __shfl_xor_sync(0xffffffffu, tmax, 2));
            tmax = fmaxf(tmax, __shfl_xor_sync(0xffffffffu, tmax, 1));

            float mn = fmaxf(mrow[i], tmax);
            float sum = 0.f;
#pragma unroll
            for (int j = 0; j < 4; j++) {
                float p = __expf(s[i][j] - mn);
                s[i][j] = p;
                sum += p;
            }
            sum += __shfl_xor_sync(0xffffffffu, sum, 8);
            sum += __shfl_xor_sync(0xffffffffu, sum, 4);
            sum += __shfl_xor_sync(0xffffffffu, sum, 2);
            sum += __shfl_xor_sync(0xffffffffu, sum, 1);

            float sc = __expf(mrow[i] - mn);
            lrow[i] = lrow[i] * sc + sum;
            mrow[i] = mn;
#pragma unroll
            for (int j = 0; j < 4; j++) O[i][j] *= sc;

#pragma unroll
            for (int j = 0; j < 4; j++)
                Psh[(tx * 4 + j) * QS + ty * 8 + i] = s[i][j];
        }
        __syncthreads();

#pragma unroll 8
        for (int k = 0; k < 64; k++) {
            float4 a0 = *(const float4*)&Psh[k * QS + ty * 8];
            float4 a1 = *(const float4*)&Psh[k * QS + ty * 8 + 4];
            float4 b  = *(const float4*)&Vsh[k * CS + tx * 4];
            float a[8]  = {a0.x, a0.y, a0.z, a0.w, a1.x, a1.y, a1.z, a1.w};
            float bv[4] = {b.x, b.y, b.z, b.w};
#pragma unroll
            for (int i = 0; i < 8; i++)
#pragma unroll
                for (int j = 0; j < 4; j++)
                    O[i][j] = fmaf(a[i], bv[j], O[i][j]);
        }
        __syncthreads();
    }

    const int bb = bh >> 4, h = bh & 15;
#pragma unroll
    for (int i = 0; i < 8; i++) {
        float inv = 1.f / lrow[i];
        size_t idx = ((size_t)(bb * SEQ + q0 + ty * 8 + i)) * DMODEL + h * DHEAD + tx * 4;
        *(float4*)(out + idx) = make_float4(O[i][0] * inv, O[i][1] * inv,
                                            O[i][2] * inv, O[i][3] * inv);
    }
}

// ---------------------------------------------------------------------------
extern "C" void kernel_launch(void* const* d_in, const int* in_sizes, int n_in,
                              void* d_out, int out_size)
{
    const float* X  = (const float*)d_in[0];
    const float* Wq = (const float*)d_in[1];
    const float* Wk = (const float*)d_in[2];
    const float* Wv = (const float*)d_in[3];
    float* out = (float*)d_out;

    cudaFuncSetAttribute(qkv_mma_kernel,
                         cudaFuncAttributeMaxDynamicSharedMemorySize, GEMM_SMEM);
    cudaFuncSetAttribute(attn_kernel,
                         cudaFuncAttributeMaxDynamicSharedMemorySize, ATTN_SMEM);

    split_x_kernel<<<(MTOT * DMODEL) / (256 * 4), 256>>>(X);
    split_wt_kernel<<<dim3(32, 32, 3), dim3(32, 8)>>>(Wq, Wk, Wv);

    dim3 ggrid(DMODEL / 128, MTOT / 128, 3);   // 8 x 64 x 3
    qkv_mma_kernel<<<ggrid, 256, GEMM_SMEM>>>();

    dim3 agrid(SEQ / BR, NBH);                 // 16 x 64
    attn_kernel<<<agrid, 256, ATTN_SMEM>>>(out);
}

// round 5
// speedup vs baseline: 2.4227x; 1.7259x over previous
#include <cuda_runtime.h>
#include <cuda_fp16.h>
#include <cstdint>
#include <math.h>

#define BATCH  4
#define SEQ    2048
#define DMODEL 1024
#define NHEADS 16
#define DHEAD  64
#define NBH    (BATCH * NHEADS)   // 64
#define MTOT   (BATCH * SEQ)      // 8192

// ---------------- scratch (static device arrays; allocation-free) ----------
// Q,K: [bh][s][d] (d contiguous), Q pre-scaled by 0.125. V: [bh][d][s].
__device__ __half g_Qhi[(size_t)NBH * SEQ * DHEAD];
__device__ __half g_Qlo[(size_t)NBH * SEQ * DHEAD];
__device__ __half g_Khi[(size_t)NBH * SEQ * DHEAD];
__device__ __half g_Klo[(size_t)NBH * SEQ * DHEAD];
__device__ __half g_Vhi[(size_t)NBH * DHEAD * SEQ];
__device__ __half g_Vlo[(size_t)NBH * DHEAD * SEQ];

__device__ __half g_Xhi[(size_t)MTOT * DMODEL];
__device__ __half g_Xlo[(size_t)MTOT * DMODEL];
__device__ __half g_WThi[(size_t)3 * DMODEL * DMODEL];  // [which][n][k]
__device__ __half g_WTlo[(size_t)3 * DMODEL * DMODEL];

// ---------------- helpers ---------------------------------------------------
__device__ __forceinline__ void cp16(uint32_t dst, const void* src) {
    asm volatile("cp.async.cg.shared.global [%0], [%1], 16;" :: "r"(dst), "l"(src));
}
#define CP_COMMIT() asm volatile("cp.async.commit_group;" ::: "memory")
#define CP_WAIT(n)  asm volatile("cp.async.wait_group %0;" :: "n"(n) : "memory")

__device__ __forceinline__ uint32_t smem_u32(const void* p) {
    uint32_t a;
    asm("{ .reg .u64 t; cvta.to.shared.u64 t, %1; cvt.u32.u64 %0, t; }" : "=r"(a) : "l"(p));
    return a;
}
__device__ __forceinline__ uint32_t ld32sh(const __half* p) {
    return *(const uint32_t*)p;
}
__device__ __forceinline__ void mma16816(float* c, const uint32_t* a, const uint32_t* b) {
    asm volatile("mma.sync.aligned.m16n8k16.row.col.f32.f16.f16.f32 "
                 "{%0,%1,%2,%3}, {%4,%5,%6,%7}, {%8,%9}, {%0,%1,%2,%3};"
                 : "+f"(c[0]), "+f"(c[1]), "+f"(c[2]), "+f"(c[3])
                 : "r"(a[0]), "r"(a[1]), "r"(a[2]), "r"(a[3]), "r"(b[0]), "r"(b[1]));
}

// fast exp on FMA pipe: e^x for x <= ~0. rel err ~1.2e-7.
__device__ __forceinline__ float fexp(float x) {
    float t = x * 1.4426950408889634f;
    t = fmaxf(t, -30.f);
    int n = __float2int_rn(t);
    float f = t - (float)n;
    float p =               1.5403530393381610e-4f;
    p = fmaf(p, f, 1.3333558146428443e-3f);
    p = fmaf(p, f, 9.6181291076284772e-3f);
    p = fmaf(p, f, 5.5504108664821580e-2f);
    p = fmaf(p, f, 2.4022650695910071e-1f);
    p = fmaf(p, f, 6.9314718055994531e-1f);
    p = fmaf(p, f, 1.0f);
    return p * __int_as_float((n + 127) << 23);
}

// ---------------- conversion kernels ---------------------------------------
__global__ void split_x_kernel(const float* __restrict__ X)
{
    size_t i = ((size_t)blockIdx.x * blockDim.x + threadIdx.x) * 4;
    float4 v = *(const float4*)(X + i);
    float f[4] = {v.x, v.y, v.z, v.w};
#pragma unroll
    for (int j = 0; j < 4; j++) {
        __half hi = __float2half_rn(f[j]);
        g_Xhi[i + j] = hi;
        g_Xlo[i + j] = __float2half_rn(f[j] - __half2float(hi));
    }
}

__global__ void split_wt_kernel(const float* __restrict__ Wq,
                                const float* __restrict__ Wk,
                                const float* __restrict__ Wv)
{
    __shared__ float t[32][33];
    const float* W = (blockIdx.z == 0) ? Wq : (blockIdx.z == 1) ? Wk : Wv;
    int tx = threadIdx.x, ty = threadIdx.y;
    int n = blockIdx.x * 32 + tx;
#pragma unroll
    for (int i = 0; i < 4; i++) {
        int k = blockIdx.y * 32 + ty + i * 8;
        t[ty + i * 8][tx] = W[(size_t)k * DMODEL + n];
    }
    __syncthreads();
    size_t base = (size_t)blockIdx.z * DMODEL * DMODEL;
#pragma unroll
    for (int i = 0; i < 4; i++) {
        int nn = blockIdx.x * 32 + ty + i * 8;
        int kk = blockIdx.y * 32 + tx;
        float f = t[tx][ty + i * 8];
        __half hi = __float2half_rn(f);
        g_WThi[base + (size_t)nn * DMODEL + kk] = hi;
        g_WTlo[base + (size_t)nn * DMODEL + kk] = __float2half_rn(f - __half2float(hi));
    }
}

// ---------------- mma.sync split-fp16 projection GEMM ----------------------
constexpr int GKC = 32;
constexpr int NCHUNK = DMODEL / GKC;       // 32
constexpr int SST = 40;
constexpr uint32_t AHI = 0;
constexpr uint32_t ALO = 128 * SST * 2;
constexpr uint32_t BHI = 2 * 128 * SST * 2;
constexpr uint32_t BLO = 3 * 128 * SST * 2;
constexpr uint32_t STAGE = 4 * 128 * SST * 2;      // 40960
constexpr uint32_t GEMM_SMEM = 2 * STAGE;          // 81920

__global__ __launch_bounds__(256, 2)
void qkv_mma_kernel()
{
    extern __shared__ uint8_t sm[];
    const uint32_t sb = smem_u32(sm);

    const int tid = threadIdx.x;
    const int lane = tid & 31;
    const int warp = tid >> 5;
    const int wy = warp >> 2;
    const int wx = warp & 3;
    const int gid = lane >> 2;
    const int tig = lane & 3;

    const int which = blockIdx.z;
    const int n0 = blockIdx.x * 128;
    const int m0 = blockIdx.y * 128;

    const __half* __restrict__ WThi = g_WThi + (size_t)which * DMODEL * DMODEL;
    const __half* __restrict__ WTlo = g_WTlo + (size_t)which * DMODEL * DMODEL;

    auto load_chunk = [&](int c, int s) {
        const uint32_t stage = sb + (uint32_t)s * STAGE;
        const int c0 = c * GKC;
#pragma unroll
        for (int it = 0; it < 2; it++) {
            int idx = tid + it * 256;
            int r = idx >> 2, kg = idx & 3;
            uint32_t doff = (uint32_t)(r * SST * 2 + kg * 16);
            size_t asrc = (size_t)(m0 + r) * DMODEL + c0 + kg * 8;
            size_t bsrc = (size_t)(n0 + r) * DMODEL + c0 + kg * 8;
            cp16(stage + AHI + doff, g_Xhi + asrc);
            cp16(stage + ALO + doff, g_Xlo + asrc);
            cp16(stage + BHI + doff, WThi + bsrc);
            cp16(stage + BLO + doff, WTlo + bsrc);
        }
    };

    float acc[4][4][4];
#pragma unroll
    for (int mt = 0; mt < 4; mt++)
#pragma unroll
        for (int nt = 0; nt < 4; nt++)
#pragma unroll
            for (int j = 0; j < 4; j++) acc[mt][nt][j] = 0.f;

    load_chunk(0, 0);
    CP_COMMIT();

    for (int c = 0; c < NCHUNK; c++) {
        const int s = c & 1;
        if (c + 1 < NCHUNK) {
            load_chunk(c + 1, s ^ 1);
            CP_COMMIT();
            CP_WAIT(1);
        } else {
            CP_WAIT(0);
        }
        __syncthreads();

        const __half* Ah = (const __half*)(sm + s * STAGE + AHI);
        const __half* Al = (const __half*)(sm + s * STAGE + ALO);
        const __half* Bh = (const __half*)(sm + s * STAGE + BHI);
        const __half* Bl = (const __half*)(sm + s * STAGE + BLO);

#pragma unroll
        for (int ks = 0; ks < 2; ks++) {
            const int kbase = ks * 16 + tig * 2;
            uint32_t bh[4][2], bl[4][2];
#pragma unroll
            for (int nt = 0; nt < 4; nt++) {
                int rb = (wx * 32 + nt * 8 + gid) * SST + kbase;
                bh[nt][0] = ld32sh(Bh + rb);
                bh[nt][1] = ld32sh(Bh + rb + 8);
                bl[nt][0] = ld32sh(Bl + rb);
                bl[nt][1] = ld32sh(Bl + rb + 8);
            }
#pragma unroll
            for (int mt = 0; mt < 4; mt++) {
                int ra = (wy * 64 + mt * 16 + gid) * SST + kbase;
                uint32_t ah[4], al[4];
                ah[0] = ld32sh(Ah + ra);
                ah[1] = ld32sh(Ah + ra + 8 * SST);
                ah[2] = ld32sh(Ah + ra + 8);
                ah[3] = ld32sh(Ah + ra + 8 * SST + 8);
                al[0] = ld32sh(Al + ra);
                al[1] = ld32sh(Al + ra + 8 * SST);
                al[2] = ld32sh(Al + ra + 8);
                al[3] = ld32sh(Al + ra + 8 * SST + 8);
#pragma unroll
                for (int nt = 0; nt < 4; nt++) {
                    mma16816(acc[mt][nt], ah, bh[nt]);
                    mma16816(acc[mt][nt], ah, bl[nt]);
                    mma16816(acc[mt][nt], al, bh[nt]);
                }
            }
        }
        __syncthreads();
    }

    // ---- epilogue: emit fp16 hi/lo in attention-ready layouts -------------
#pragma unroll
    for (int mt = 0; mt < 4; mt++) {
#pragma unroll
        for (int hr = 0; hr < 2; hr++) {
            const int m = m0 + wy * 64 + mt * 16 + gid + hr * 8;
            const int bbp = m >> 11;
            const int sIdx = m & 2047;
#pragma unroll
            for (int nt = 0; nt < 4; nt++) {
                const int n = n0 + wx * 32 + nt * 8 + tig * 2;
                const int h = n >> 6, d = n & 63;
                float v0 = acc[mt][nt][hr * 2 + 0];
                float v1 = acc[mt][nt][hr * 2 + 1];
                if (which == 0) { v0 *= 0.125f; v1 *= 0.125f; }   // fold 1/sqrt(Dh) into Q
                __half h0 = __float2half_rn(v0), h1 = __float2half_rn(v1);
                __half e0 = __float2half_rn(v0 - __half2float(h0));
                __half e1 = __float2half_rn(v1 - __half2float(h1));
                if (which < 2) {
                    __half* hip = (which == 0) ? g_Qhi : g_Khi;
                    __half* lop = (which == 0) ? g_Qlo : g_Klo;
                    size_t idx = ((size_t)(bbp * NHEADS + h) * SEQ + sIdx) * DHEAD + d;
                    *(__half2*)(hip + idx) = __halves2half2(h0, h1);
                    *(__half2*)(lop + idx) = __halves2half2(e0, e1);
                } else {
                    size_t idx = ((size_t)(bbp * NHEADS + h) * DHEAD + d) * SEQ + sIdx;
                    g_Vhi[idx] = h0; g_Vhi[idx + SEQ] = h1;
                    g_Vlo[idx] = e0; g_Vlo[idx + SEQ] = e1;
                }
            }
        }
    }
}

// ---------------------------------------------------------------------------
// Flash attention with mma.sync split-fp16 + polynomial exp.
// Block: 128 queries; 8 warps, each owns 16 rows x all 64 keys.
// ---------------------------------------------------------------------------
constexpr int AST = 72;                       // smem row stride in halves
constexpr uint32_t QHI_O = 0;
constexpr uint32_t QLO_O = 18432;
constexpr uint32_t STG_O = 36864;             // 2 stages of K/V
constexpr uint32_t STGSZ = 36864;             // KH/KL/VH/VL x 9216
constexpr uint32_t KH_O = 0, KL_O = 9216, VH_O = 18432, VL_O = 27648;
constexpr uint32_t PHI_O = 110592;
constexpr uint32_t PLO_O = 129024;
constexpr uint32_t ATTN_SMEM = 147456;

__global__ __launch_bounds__(256, 1)
void attn_mma_kernel(float* __restrict__ out)
{
    extern __shared__ uint8_t sm[];
    const uint32_t sb = smem_u32(sm);

    const int tid = threadIdx.x;
    const int lane = tid & 31;
    const int w = tid >> 5;
    const int gid = lane >> 2;
    const int tig = lane & 3;
    const int bh = blockIdx.y;
    const int qt = (gridDim.x - 1) - blockIdx.x;   // heavy blocks first
    const int q0 = qt * 128;
    const int bb = bh >> 4, h = bh & 15;

    // ---- Q tile load (hi+lo) ---------------------------------------------
#pragma unroll
    for (int it = 0; it < 8; it++) {
        int comp = it >> 2;
        int r = (it & 3) * 32 + (tid >> 3);
        int g = tid & 7;
        uint32_t dst = sb + (comp ? QLO_O : QHI_O) + (uint32_t)(r * 144 + g * 16);
        const __half* src = (comp ? g_Qlo : g_Qhi) +
                            ((size_t)bh * SEQ + q0 + r) * DHEAD + g * 8;
        cp16(dst, src);
    }

    auto load_kv = [&](int kt, int s) {
        uint32_t stage = sb + STG_O + (uint32_t)s * STGSZ;
#pragma unroll
        for (int it = 0; it < 8; it++) {
            int comp = it >> 1;
            int r = (it & 1) * 32 + (tid >> 3);
            int g = tid & 7;
            uint32_t dst = stage + (uint32_t)comp * 9216u + (uint32_t)(r * 144 + g * 16);
            const __half* src;
            if (comp == 0)      src = g_Khi + ((size_t)bh * SEQ + kt * 64 + r) * DHEAD + g * 8;
            else if (comp == 1) src = g_Klo + ((size_t)bh * SEQ + kt * 64 + r) * DHEAD + g * 8;
            else if (comp == 2) src = g_Vhi + ((size_t)bh * DHEAD + r) * SEQ + kt * 64 + g * 8;
            else                src = g_Vlo + ((size_t)bh * DHEAD + r) * SEQ + kt * 64 + g * 8;
            cp16(dst, src);
        }
    };

    load_kv(0, 0);
    CP_COMMIT();

    float m0 = -1e30f, m1 = -1e30f, l0 = 0.f, l1 = 0.f;
    float oacc[8][4];
#pragma unroll
    for (int nt = 0; nt < 8; nt++)
#pragma unroll
        for (int j = 0; j < 4; j++) oacc[nt][j] = 0.f;

    const int ktmax = min(2 * qt + 2, SEQ / 64 - 1);
    const int rowbase = w * 16 + gid;

    for (int kt = 0; kt <= ktmax; kt++) {
        const int s = kt & 1;
        if (kt) __syncthreads();                  // stage s^1 free for reuse
        if (kt < ktmax) {
            load_kv(kt + 1, s ^ 1);
            CP_COMMIT();
            CP_WAIT(1);
        } else {
            CP_WAIT(0);
        }
        __syncthreads();

        const __half* Qh = (const __half*)(sm + QHI_O);
        const __half* Ql = (const __half*)(sm + QLO_O);
        const __half* Kh = (const __half*)(sm + STG_O + s * STGSZ + KH_O);
        const __half* Kl = (const __half*)(sm + STG_O + s * STGSZ + KL_O);
        const __half* Vh = (const __half*)(sm + STG_O + s * STGSZ + VH_O);
        const __half* Vl = (const __half*)(sm + STG_O + s * STGSZ + VL_O);

        // ---- S = Q K^T (split fp16, fp32 acc) ----------------------------
        float sacc[8][4];
#pragma unroll
        for (int nt = 0; nt < 8; nt++)
#pragma unroll
            for (int j = 0; j < 4; j++) sacc[nt][j] = 0.f;

#pragma unroll
        for (int ks = 0; ks < 4; ks++) {
            const int kb = ks * 16 + tig * 2;
            const int ra = rowbase * AST + kb;
            uint32_t ah[4], al[4];
            ah[0] = ld32sh(Qh + ra);
            ah[1] = ld32sh(Qh + ra + 8 * AST);
            ah[2] = ld32sh(Qh + ra + 8);
            ah[3] = ld32sh(Qh + ra + 8 * AST + 8);
            al[0] = ld32sh(Ql + ra);
            al[1] = ld32sh(Ql + ra + 8 * AST);
            al[2] = ld32sh(Ql + ra + 8);
            al[3] = ld32sh(Ql + ra + 8 * AST + 8);
#pragma unroll
            for (int nt = 0; nt < 8; nt++) {
                const int rb = (nt * 8 + gid) * AST + kb;
                uint32_t bhh[2] = { ld32sh(Kh + rb), ld32sh(Kh + rb + 8) };
                uint32_t bll[2] = { ld32sh(Kl + rb), ld32sh(Kl + rb + 8) };
                mma16816(sacc[nt], ah, bhh);
                mma16816(sacc[nt], ah, bll);
                mma16816(sacc[nt], al, bhh);
            }
        }

        // ---- mask (only last ~3 tiles can clip): valid iff k <= q+1 ------
        if (kt >= 2 * qt) {
            const int qg0 = q0 + rowbase, qg1 = qg0 + 8;
#pragma unroll
            for (int nt = 0; nt < 8; nt++) {
                const int c0 = kt * 64 + nt * 8 + tig * 2;
                if (c0     > qg0 + 1) sacc[nt][0] = -1e30f;
                if (c0 + 1 > qg0 + 1) sacc[nt][1] = -1e30f;
                if (c0     > qg1 + 1) sacc[nt][2] = -1e30f;
                if (c0 + 1 > qg1 + 1) sacc[nt][3] = -1e30f;
            }
        }

        // ---- online softmax (poly exp on FMA pipe) -----------------------
        float r0 = -1e30f, r1 = -1e30f;
#pragma unroll
        for (int nt = 0; nt < 8; nt++) {
            r0 = fmaxf(r0, fmaxf(sacc[nt][0], sacc[nt][1]));
            r1 = fmaxf(r1, fmaxf(sacc[nt][2], sacc[nt][3]));
        }
        r0 = fmaxf(r0, __shfl_xor_sync(0xffffffffu, r0, 1));
        r0 = fmaxf(r0, __shfl_xor_sync(0xffffffffu, r0, 2));
        r1 = fmaxf(r1, __shfl_xor_sync(0xffffffffu, r1, 1));
        r1 = fmaxf(r1, __shfl_xor_sync(0xffffffffu, r1, 2));

        const float mn0 = fmaxf(m0, r0), mn1 = fmaxf(m1, r1);
        const float sc0 = fexp(m0 - mn0), sc1 = fexp(m1 - mn1);
        m0 = mn0; m1 = mn1;

        __half* Phw = (__half*)(sm + PHI_O);
        __half* Plw = (__half*)(sm + PLO_O);
        float rs0 = 0.f, rs1 = 0.f;
#pragma unroll
        for (int nt = 0; nt < 8; nt++) {
            float p0 = fexp(sacc[nt][0] - mn0);
            float p1 = fexp(sacc[nt][1] - mn0);
            float p2 = fexp(sacc[nt][2] - mn1);
            float p3 = fexp(sacc[nt][3] - mn1);
            rs0 += p0 + p1;
            rs1 += p2 + p3;
            __half h0 = __float2half_rn(p0), h1 = __float2half_rn(p1);
            __half h2 = __float2half_rn(p2), h3 = __float2half_rn(p3);
            __half e0 = __float2half_rn(p0 - __half2float(h0));
            __half e1 = __float2half_rn(p1 - __half2float(h1));
            __half e2 = __float2half_rn(p2 - __half2float(h2));
            __half e3 = __float2half_rn(p3 - __half2float(h3));
            const int i0 = rowbase * AST + nt * 8 + tig * 2;
            const int i1 = i0 + 8 * AST;
            *(__half2*)(Phw + i0) = __halves2half2(h0, h1);
            *(__half2*)(Phw + i1) = __halves2half2(h2, h3);
            *(__half2*)(Plw + i0) = __halves2half2(e0, e1);
            *(__half2*)(Plw + i1) = __halves2half2(e2, e3);
        }
        rs0 += __shfl_xor_sync(0xffffffffu, rs0, 1);
        rs0 += __shfl_xor_sync(0xffffffffu, rs0, 2);
        rs1 += __shfl_xor_sync(0xffffffffu, rs1, 1);
        rs1 += __shfl_xor_sync(0xffffffffu, rs1, 2);
        l0 = l0 * sc0 + rs0;
        l1 = l1 * sc1 + rs1;
#pragma unroll
        for (int nt = 0; nt < 8; nt++) {
            oacc[nt][0] *= sc0; oacc[nt][1] *= sc0;
            oacc[nt][2] *= sc1; oacc[nt][3] *= sc1;
        }

        __syncwarp();   // P visible within warp (P never crosses warps)

        // ---- O += P V (split fp16) ---------------------------------------
        const __half* Ph = (const __half*)(sm + PHI_O);
        const __half* Pl = (const __half*)(sm + PLO_O);
#pragma unroll
        for (int ks = 0; ks < 4; ks++) {
            const int kb = ks * 16 + tig * 2;
            const int ra = rowbase * AST + kb;
            uint32_t ah[4], al[4];
            ah[0] = ld32sh(Ph + ra);
            ah[1] = ld32sh(Ph + ra + 8 * AST);
            ah[2] = ld32sh(Ph + ra + 8);
            ah[3] = ld32sh(Ph + ra + 8 * AST + 8);
            al[0] = ld32sh(Pl + ra);
            al[1] = ld32sh(Pl + ra + 8 * AST);
            al[2] = ld32sh(Pl + ra + 8);
            al[3] = ld32sh(Pl + ra + 8 * AST + 8);
#pragma unroll
            for (int nt = 0; nt < 8; nt++) {
                const int rb = (nt * 8 + gid) * AST + kb;
                uint32_t bhh[2] = { ld32sh(Vh + rb), ld32sh(Vh + rb + 8) };
                uint32_t bll[2] = { ld32sh(Vl + rb), ld32sh(Vl + rb + 8) };
                mma16816(oacc[nt], ah, bhh);
                mma16816(oacc[nt], ah, bll);
                mma16816(oacc[nt], al, bhh);
            }
        }
        __syncwarp();   // P reads done before next tile overwrites
    }

    // ---- epilogue: out[b][s][h*64+d] --------------------------------------
    const float inv0 = 1.f / l0, inv1 = 1.f / l1;
    const int s0 = q0 + rowbase;
#pragma unroll
    for (int nt = 0; nt < 8; nt++) {
        const int d = h * DHEAD + nt * 8 + tig * 2;
        size_t i0 = ((size_t)(bb * SEQ + s0)) * DMODEL + d;
        size_t i1 = ((size_t)(bb * SEQ + s0 + 8)) * DMODEL + d;
        *(float2*)(out + i0) = make_float2(oacc[nt][0] * inv0, oacc[nt][1] * inv0);
        *(float2*)(out + i1) = make_float2(oacc[nt][2] * inv1, oacc[nt][3] * inv1);
    }
}

// ---------------------------------------------------------------------------
extern "C" void kernel_launch(void* const* d_in, const int* in_sizes, int n_in,
                              void* d_out, int out_size)
{
    const float* X  = (const float*)d_in[0];
    const float* Wq = (const float*)d_in[1];
    const float* Wk = (const float*)d_in[2];
    const float* Wv = (const float*)d_in[3];
    float* out = (float*)d_out;

    cudaFuncSetAttribute(qkv_mma_kernel,
                         cudaFuncAttributeMaxDynamicSharedMemorySize, GEMM_SMEM);
    cudaFuncSetAttribute(attn_mma_kernel,
                         cudaFuncAttributeMaxDynamicSharedMemorySize, ATTN_SMEM);

    split_x_kernel<<<(MTOT * DMODEL) / (256 * 4), 256>>>(X);
    split_wt_kernel<<<dim3(32, 32, 3), dim3(32, 8)>>>(Wq, Wk, Wv);

    dim3 ggrid(DMODEL / 128, MTOT / 128, 3);   // 8 x 64 x 3
    qkv_mma_kernel<<<ggrid, 256, GEMM_SMEM>>>();

    dim3 agrid(SEQ / 128, NBH);                // 16 x 64
    attn_mma_kernel<<<agrid, 256, ATTN_SMEM>>>(out);
}

// round 7
// speedup vs baseline: 2.5124x; 1.0370x over previous
#include <cuda_runtime.h>
#include <cuda_fp16.h>
#include <cstdint>
#include <math.h>

#define BATCH  4
#define SEQ    2048
#define DMODEL 1024
#define NHEADS 16
#define DHEAD  64
#define NBH    (BATCH * NHEADS)   // 64
#define MTOT   (BATCH * SEQ)      // 8192

// ---------------- scratch (static device arrays; allocation-free) ----------
// Q,K: [bh][s][d] (d contiguous), Q pre-scaled by 0.125. V: [bh][d][s].
__device__ __half g_Qhi[(size_t)NBH * SEQ * DHEAD];
__device__ __half g_Qlo[(size_t)NBH * SEQ * DHEAD];
__device__ __half g_Khi[(size_t)NBH * SEQ * DHEAD];
__device__ __half g_Klo[(size_t)NBH * SEQ * DHEAD];
__device__ __half g_Vhi[(size_t)NBH * DHEAD * SEQ];
__device__ __half g_Vlo[(size_t)NBH * DHEAD * SEQ];

__device__ __half g_Xhi[(size_t)MTOT * DMODEL];
__device__ __half g_Xlo[(size_t)MTOT * DMODEL];
__device__ __half g_WThi[(size_t)3 * DMODEL * DMODEL];  // [which][n][k]
__device__ __half g_WTlo[(size_t)3 * DMODEL * DMODEL];

// ---------------- helpers ---------------------------------------------------
__device__ __forceinline__ void cp16(uint32_t dst, const void* src) {
    asm volatile("cp.async.cg.shared.global [%0], [%1], 16;" :: "r"(dst), "l"(src));
}
#define CP_COMMIT() asm volatile("cp.async.commit_group;" ::: "memory")
#define CP_WAIT(n)  asm volatile("cp.async.wait_group %0;" :: "n"(n) : "memory")

__device__ __forceinline__ uint32_t smem_u32(const void* p) {
    uint32_t a;
    asm("{ .reg .u64 t; cvta.to.shared.u64 t, %1; cvt.u32.u64 %0, t; }" : "=r"(a) : "l"(p));
    return a;
}
__device__ __forceinline__ uint32_t ld32sh(const __half* p) {
    return *(const uint32_t*)p;
}
__device__ __forceinline__ void mma16816(float* c, const uint32_t* a, const uint32_t* b) {
    asm volatile("mma.sync.aligned.m16n8k16.row.col.f32.f16.f16.f32 "
                 "{%0,%1,%2,%3}, {%4,%5,%6,%7}, {%8,%9}, {%0,%1,%2,%3};"
                 : "+f"(c[0]), "+f"(c[1]), "+f"(c[2]), "+f"(c[3])
                 : "r"(a[0]), "r"(a[1]), "r"(a[2]), "r"(a[3]), "r"(b[0]), "r"(b[1]));
}
__device__ __forceinline__ uint32_t packh2(float a, float b) {
    __half2 h = __halves2half2(__float2half_rn(a), __float2half_rn(b));
    return *(uint32_t*)&h;
}

// fast exp on FMA pipe: e^x for x <= ~0. rel err ~1.2e-7.
__device__ __forceinline__ float fexp(float x) {
    float t = x * 1.4426950408889634f;
    t = fmaxf(t, -30.f);
    int n = __float2int_rn(t);
    float f = t - (float)n;
    float p =               1.5403530393381610e-4f;
    p = fmaf(p, f, 1.3333558146428443e-3f);
    p = fmaf(p, f, 9.6181291076284772e-3f);
    p = fmaf(p, f, 5.5504108664821580e-2f);
    p = fmaf(p, f, 2.4022650695910071e-1f);
    p = fmaf(p, f, 6.9314718055994531e-1f);
    p = fmaf(p, f, 1.0f);
    return p * __int_as_float((n + 127) << 23);
}

// ---------------- conversion kernels ---------------------------------------
__global__ void split_x_kernel(const float* __restrict__ X)
{
    size_t i = ((size_t)blockIdx.x * blockDim.x + threadIdx.x) * 4;
    float4 v = *(const float4*)(X + i);
    float f[4] = {v.x, v.y, v.z, v.w};
#pragma unroll
    for (int j = 0; j < 4; j++) {
        __half hi = __float2half_rn(f[j]);
        g_Xhi[i + j] = hi;
        g_Xlo[i + j] = __float2half_rn(f[j] - __half2float(hi));
    }
}

__global__ void split_wt_kernel(const float* __restrict__ Wq,
                                const float* __restrict__ Wk,
                                const float* __restrict__ Wv)
{
    __shared__ float t[32][33];
    const float* W = (blockIdx.z == 0) ? Wq : (blockIdx.z == 1) ? Wk : Wv;
    int tx = threadIdx.x, ty = threadIdx.y;
    int n = blockIdx.x * 32 + tx;
#pragma unroll
    for (int i = 0; i < 4; i++) {
        int k = blockIdx.y * 32 + ty + i * 8;
        t[ty + i * 8][tx] = W[(size_t)k * DMODEL + n];
    }
    __syncthreads();
    size_t base = (size_t)blockIdx.z * DMODEL * DMODEL;
#pragma unroll
    for (int i = 0; i < 4; i++) {
        int nn = blockIdx.x * 32 + ty + i * 8;
        int kk = blockIdx.y * 32 + tx;
        float f = t[tx][ty + i * 8];
        __half hi = __float2half_rn(f);
        g_WThi[base + (size_t)nn * DMODEL + kk] = hi;
        g_WTlo[base + (size_t)nn * DMODEL + kk] = __float2half_rn(f - __half2float(hi));
    }
}

// ---------------- mma.sync split-fp16 projection GEMM ----------------------
constexpr int GKC = 32;
constexpr int NCHUNK = DMODEL / GKC;       // 32
constexpr int SST = 40;
constexpr uint32_t AHI = 0;
constexpr uint32_t ALO = 128 * SST * 2;
constexpr uint32_t BHI = 2 * 128 * SST * 2;
constexpr uint32_t BLO = 3 * 128 * SST * 2;
constexpr uint32_t STAGE = 4 * 128 * SST * 2;      // 40960
constexpr uint32_t GEMM_SMEM = 2 * STAGE;          // 81920

__global__ __launch_bounds__(256, 2)
void qkv_mma_kernel()
{
    extern __shared__ uint8_t sm[];
    const uint32_t sb = smem_u32(sm);

    const int tid = threadIdx.x;
    const int lane = tid & 31;
    const int warp = tid >> 5;
    const int wy = warp >> 2;
    const int wx = warp & 3;
    const int gid = lane >> 2;
    const int tig = lane & 3;

    const int which = blockIdx.z;
    const int n0 = blockIdx.x * 128;
    const int m0 = blockIdx.y * 128;

    const __half* __restrict__ WThi = g_WThi + (size_t)which * DMODEL * DMODEL;
    const __half* __restrict__ WTlo = g_WTlo + (size_t)which * DMODEL * DMODEL;

    auto load_chunk = [&](int c, int s) {
        const uint32_t stage = sb + (uint32_t)s * STAGE;
        const int c0 = c * GKC;
#pragma unroll
        for (int it = 0; it < 2; it++) {
            int idx = tid + it * 256;
            int r = idx >> 2, kg = idx & 3;
            uint32_t doff = (uint32_t)(r * SST * 2 + kg * 16);
            size_t asrc = (size_t)(m0 + r) * DMODEL + c0 + kg * 8;
            size_t bsrc = (size_t)(n0 + r) * DMODEL + c0 + kg * 8;
            cp16(stage + AHI + doff, g_Xhi + asrc);
            cp16(stage + ALO + doff, g_Xlo + asrc);
            cp16(stage + BHI + doff, WThi + bsrc);
            cp16(stage + BLO + doff, WTlo + bsrc);
        }
    };

    float acc[4][4][4];
#pragma unroll
    for (int mt = 0; mt < 4; mt++)
#pragma unroll
        for (int nt = 0; nt < 4; nt++)
#pragma unroll
            for (int j = 0; j < 4; j++) acc[mt][nt][j] = 0.f;

    load_chunk(0, 0);
    CP_COMMIT();

    for (int c = 0; c < NCHUNK; c++) {
        const int s = c & 1;
        if (c + 1 < NCHUNK) {
            load_chunk(c + 1, s ^ 1);
            CP_COMMIT();
            CP_WAIT(1);
        } else {
            CP_WAIT(0);
        }
        __syncthreads();

        const __half* Ah = (const __half*)(sm + s * STAGE + AHI);
        const __half* Al = (const __half*)(sm + s * STAGE + ALO);
        const __half* Bh = (const __half*)(sm + s * STAGE + BHI);
        const __half* Bl = (const __half*)(sm + s * STAGE + BLO);

#pragma unroll
        for (int ks = 0; ks < 2; ks++) {
            const int kbase = ks * 16 + tig * 2;
            uint32_t bh[4][2], bl[4][2];
#pragma unroll
            for (int nt = 0; nt < 4; nt++) {
                int rb = (wx * 32 + nt * 8 + gid) * SST + kbase;
                bh[nt][0] = ld32sh(Bh + rb);
                bh[nt][1] = ld32sh(Bh + rb + 8);
                bl[nt][0] = ld32sh(Bl + rb);
                bl[nt][1] = ld32sh(Bl + rb + 8);
            }
#pragma unroll
            for (int mt = 0; mt < 4; mt++) {
                int ra = (wy * 64 + mt * 16 + gid) * SST + kbase;
                uint32_t ah[4], al[4];
                ah[0] = ld32sh(Ah + ra);
                ah[1] = ld32sh(Ah + ra + 8 * SST);
                ah[2] = ld32sh(Ah + ra + 8);
                ah[3] = ld32sh(Ah + ra + 8 * SST + 8);
                al[0] = ld32sh(Al + ra);
                al[1] = ld32sh(Al + ra + 8 * SST);
                al[2] = ld32sh(Al + ra + 8);
                al[3] = ld32sh(Al + ra + 8 * SST + 8);
#pragma unroll
                for (int nt = 0; nt < 4; nt++) {
                    mma16816(acc[mt][nt], ah, bh[nt]);
                    mma16816(acc[mt][nt], ah, bl[nt]);
                    mma16816(acc[mt][nt], al, bh[nt]);
                }
            }
        }
        __syncthreads();
    }

    // ---- epilogue: emit fp16 hi/lo in attention-ready layouts -------------
#pragma unroll
    for (int mt = 0; mt < 4; mt++) {
#pragma unroll
        for (int hr = 0; hr < 2; hr++) {
            const int m = m0 + wy * 64 + mt * 16 + gid + hr * 8;
            const int bbp = m >> 11;
            const int sIdx = m & 2047;
#pragma unroll
            for (int nt = 0; nt < 4; nt++) {
                const int n = n0 + wx * 32 + nt * 8 + tig * 2;
                const int h = n >> 6, d = n & 63;
                float v0 = acc[mt][nt][hr * 2 + 0];
                float v1 = acc[mt][nt][hr * 2 + 1];
                if (which == 0) { v0 *= 0.125f; v1 *= 0.125f; }   // fold 1/sqrt(Dh) into Q
                __half h0 = __float2half_rn(v0), h1 = __float2half_rn(v1);
                __half e0 = __float2half_rn(v0 - __half2float(h0));
                __half e1 = __float2half_rn(v1 - __half2float(h1));
                if (which < 2) {
                    __half* hip = (which == 0) ? g_Qhi : g_Khi;
                    __half* lop = (which == 0) ? g_Qlo : g_Klo;
                    size_t idx = ((size_t)(bbp * NHEADS + h) * SEQ + sIdx) * DHEAD + d;
                    *(__half2*)(hip + idx) = __halves2half2(h0, h1);
                    *(__half2*)(lop + idx) = __halves2half2(e0, e1);
                } else {
                    size_t idx = ((size_t)(bbp * NHEADS + h) * DHEAD + d) * SEQ + sIdx;
                    g_Vhi[idx] = h0; g_Vhi[idx + SEQ] = h1;
                    g_Vlo[idx] = e0; g_Vlo[idx + SEQ] = e1;
                }
            }
        }
    }
}

// ---------------------------------------------------------------------------
// Flash attention, mma.sync, P kept in registers (S-acc frag == PV A-frag).
// CTA: 128 threads (4 warps), 64 query rows; 2 CTAs/SM.
// ---------------------------------------------------------------------------
constexpr int AST = 72;                       // smem row stride in halves
constexpr uint32_t QHI_O = 0;
constexpr uint32_t QLO_O = 9216;
constexpr uint32_t STG_O = 18432;
constexpr uint32_t STGSZ = 36864;             // KH/KL/VH/VL x 9216
constexpr uint32_t KH_O = 0, KL_O = 9216, VH_O = 18432, VL_O = 27648;
constexpr uint32_t ATTN_SMEM = STG_O + 2 * STGSZ;   // 92160

__global__ __launch_bounds__(128, 2)
void attn_mma_kernel(float* __restrict__ out)
{
    extern __shared__ uint8_t sm[];
    const uint32_t sb = smem_u32(sm);

    const int tid = threadIdx.x;
    const int lane = tid & 31;
    const int w = tid >> 5;                        // 0..3
    const int gid = lane >> 2;
    const int tig = lane & 3;
    const int bh = blockIdx.y;
    const int qt = (gridDim.x - 1) - blockIdx.x;   // heavy blocks first
    const int q0 = qt * 64;
    const int bb = bh >> 4, h = bh & 15;

    // ---- Q tile load (hi+lo): 64 rows x 64 d -----------------------------
#pragma unroll
    for (int comp = 0; comp < 2; comp++) {
#pragma unroll
        for (int it = 0; it < 4; it++) {
            int idx = tid + it * 128;          // 0..511
            int r = idx >> 3, g = idx & 7;
            uint32_t dst = sb + (comp ? QLO_O : QHI_O) + (uint32_t)(r * 144 + g * 16);
            const __half* src = (comp ? g_Qlo : g_Qhi) +
                                ((size_t)bh * SEQ + q0 + r) * DHEAD + g * 8;
            cp16(dst, src);
        }
    }

    auto load_kv = [&](int kt, int s) {
        uint32_t stage = sb + STG_O + (uint32_t)s * STGSZ;
#pragma unroll
        for (int comp = 0; comp < 4; comp++) {
#pragma unroll
            for (int it = 0; it < 4; it++) {
                int idx = tid + it * 128;
                int r = idx >> 3, g = idx & 7;
                uint32_t dst = stage + (uint32_t)comp * 9216u + (uint32_t)(r * 144 + g * 16);
                const __half* src;
                if (comp == 0)      src = g_Khi + ((size_t)bh * SEQ + kt * 64 + r) * DHEAD + g * 8;
                else if (comp == 1) src = g_Klo + ((size_t)bh * SEQ + kt * 64 + r) * DHEAD + g * 8;
                else if (comp == 2) src = g_Vhi + ((size_t)bh * DHEAD + r) * SEQ + kt * 64 + g * 8;
                else                src = g_Vlo + ((size_t)bh * DHEAD + r) * SEQ + kt * 64 + g * 8;
                cp16(dst, src);
            }
        }
    };

    load_kv(0, 0);
    CP_COMMIT();

    float m0 = -1e30f, m1 = -1e30f, l0 = 0.f, l1 = 0.f;
    float oacc[8][4];
#pragma unroll
    for (int nt = 0; nt < 8; nt++)
#pragma unroll
        for (int j = 0; j < 4; j++) oacc[nt][j] = 0.f;

    const int ktmax = min(qt + 1, SEQ / 64 - 1);
    const int rowbase = w * 16 + gid;

    for (int kt = 0; kt <= ktmax; kt++) {
        const int s = kt & 1;
        if (kt) __syncthreads();                  // stage s^1 free for reuse
        if (kt < ktmax) {
            load_kv(kt + 1, s ^ 1);
            CP_COMMIT();
            CP_WAIT(1);
        } else {
            CP_WAIT(0);
        }
        __syncthreads();

        const __half* Qh = (const __half*)(sm + QHI_O);
        const __half* Ql = (const __half*)(sm + QLO_O);
        const __half* Kh = (const __half*)(sm + STG_O + s * STGSZ + KH_O);
        const __half* Kl = (const __half*)(sm + STG_O + s * STGSZ + KL_O);
        const __half* Vh = (const __half*)(sm + STG_O + s * STGSZ + VH_O);
        const __half* Vl = (const __half*)(sm + STG_O + s * STGSZ + VL_O);

        // ---- S = Q K^T (split fp16, fp32 acc) ----------------------------
        float sacc[8][4];
#pragma unroll
        for (int nt = 0; nt < 8; nt++)
#pragma unroll
            for (int j = 0; j < 4; j++) sacc[nt][j] = 0.f;

#pragma unroll
        for (int ks = 0; ks < 4; ks++) {
            const int kb = ks * 16 + tig * 2;
            const int ra = rowbase * AST + kb;
            uint32_t ah[4], al[4];
            ah[0] = ld32sh(Qh + ra);
            ah[1] = ld32sh(Qh + ra + 8 * AST);
            ah[2] = ld32sh(Qh + ra + 8);
            ah[3] = ld32sh(Qh + ra + 8 * AST + 8);
            al[0] = ld32sh(Ql + ra);
            al[1] = ld32sh(Ql + ra + 8 * AST);
            al[2] = ld32sh(Ql + ra + 8);
            al[3] = ld32sh(Ql + ra + 8 * AST + 8);
#pragma unroll
            for (int nt = 0; nt < 8; nt++) {
                const int rb = (nt * 8 + gid) * AST + kb;
                uint32_t bhh[2] = { ld32sh(Kh + rb), ld32sh(Kh + rb + 8) };
                uint32_t bll[2] = { ld32sh(Kl + rb), ld32sh(Kl + rb + 8) };
                mma16816(sacc[nt], ah, bhh);
                mma16816(sacc[nt], ah, bll);
                mma16816(sacc[nt], al, bhh);
            }
        }

        // ---- mask: valid iff k <= q+1 (only kt >= qt tiles clip) ---------
        if (kt >= qt) {
            const int qg0 = q0 + rowbase, qg1 = qg0 + 8;
#pragma unroll
            for (int nt = 0; nt < 8; nt++) {
                const int c0 = kt * 64 + nt * 8 + tig * 2;
                if (c0     > qg0 + 1) sacc[nt][0] = -1e30f;
                if (c0 + 1 > qg0 + 1) sacc[nt][1] = -1e30f;
                if (c0     > qg1 + 1) sacc[nt][2] = -1e30f;
                if (c0 + 1 > qg1 + 1) sacc[nt][3] = -1e30f;
            }
        }

        // ---- online softmax (poly exp on FMA pipe) -----------------------
        float r0 = -1e30f, r1 = -1e30f;
#pragma unroll
        for (int nt = 0; nt < 8; nt++) {
            r0 = fmaxf(r0, fmaxf(sacc[nt][0], sacc[nt][1]));
            r1 = fmaxf(r1, fmaxf(sacc[nt][2], sacc[nt][3]));
        }
        r0 = fmaxf(r0, __shfl_xor_sync(0xffffffffu, r0, 1));
        r0 = fmaxf(r0, __shfl_xor_sync(0xffffffffu, r0, 2));
        r1 = fmaxf(r1, __shfl_xor_sync(0xffffffffu, r1, 1));
        r1 = fmaxf(r1, __shfl_xor_sync(0xffffffffu, r1, 2));

        const float mn0 = fmaxf(m0, r0), mn1 = fmaxf(m1, r1);
        const float sc0 = fexp(m0 - mn0), sc1 = fexp(m1 - mn1);
        m0 = mn0; m1 = mn1;

        // exp + pack P directly into PV A-operand fragments (no smem).
        // C-frag (g,k0),(g,k0+1),(g+8,k0),(g+8,k0+1) maps onto A-frag order
        // [a0=(g,klo) a1=(g+8,klo) a2=(g,khi) a3=(g+8,khi)] with nt even -> klo,
        // nt odd -> khi. No reg swap needed (verified against working GEMM).
        uint32_t pha[4][4], pla[4][4];
        float rs0 = 0.f, rs1 = 0.f;
#pragma unroll
        for (int nt = 0; nt < 8; nt++) {
            float p0 = fexp(sacc[nt][0] - mn0);
            float p1 = fexp(sacc[nt][1] - mn0);
            float p2 = fexp(sacc[nt][2] - mn1);
            float p3 = fexp(sacc[nt][3] - mn1);
            rs0 += p0 + p1;
            rs1 += p2 + p3;
            float h01 = __half2float(__float2half_rn(p0));
            float h11 = __half2float(__float2half_rn(p1));
            float h21 = __half2float(__float2half_rn(p2));
            float h31 = __half2float(__float2half_rn(p3));
            const int ks = nt >> 1, hi2 = (nt & 1) << 1;
            pha[ks][hi2 + 0] = packh2(p0, p1);            // row g
            pha[ks][hi2 + 1] = packh2(p2, p3);            // row g+8
            pla[ks][hi2 + 0] = packh2(p0 - h01, p1 - h11);
            pla[ks][hi2 + 1] = packh2(p2 - h21, p3 - h31);
        }
        // reorder halves: built as [klo rowg, klo rowg+8, khi rowg, khi rowg+8]
        // == [a0 a1 a2 a3] already. (hi2 for nt even gives slots 0,1; odd 2,3.)

        rs0 += __shfl_xor_sync(0xffffffffu, rs0, 1);
        rs0 += __shfl_xor_sync(0xffffffffu, rs0, 2);
        rs1 += __shfl_xor_sync(0xffffffffu, rs1, 1);
        rs1 += __shfl_xor_sync(0xffffffffu, rs1, 2);
        l0 = l0 * sc0 + rs0;
        l1 = l1 * sc1 + rs1;
#pragma unroll
        for (int nt = 0; nt < 8; nt++) {
            oacc[nt][0] *= sc0; oacc[nt][1] *= sc0;
            oacc[nt][2] *= sc1; oacc[nt][3] *= sc1;
        }

        // ---- O += P V (split fp16, P from registers) ---------------------
#pragma unroll
        for (int ks = 0; ks < 4; ks++) {
            const int kb = ks * 16 + tig * 2;
#pragma unroll
            for (int nt = 0; nt < 8; nt++) {
                const int rb = (nt * 8 + gid) * AST + kb;
                uint32_t bhh[2] = { ld32sh(Vh + rb), ld32sh(Vh + rb + 8) };
                uint32_t bll[2] = { ld32sh(Vl + rb), ld32sh(Vl + rb + 8) };
                mma16816(oacc[nt], pha[ks], bhh);
                mma16816(oacc[nt], pha[ks], bll);
                mma16816(oacc[nt], pla[ks], bhh);
            }
        }
    }

    // ---- epilogue: out[b][s][h*64+d] --------------------------------------
    const float inv0 = 1.f / l0, inv1 = 1.f / l1;
    const int s0 = q0 + rowbase;
#pragma unroll
    for (int nt = 0; nt < 8; nt++) {
        const int d = h * DHEAD + nt * 8 + tig * 2;
        size_t i0 = ((size_t)(bb * SEQ + s0)) * DMODEL + d;
        size_t i1 = ((size_t)(bb * SEQ + s0 + 8)) * DMODEL + d;
        *(float2*)(out + i0) = make_float2(oacc[nt][0] * inv0, oacc[nt][1] * inv0);
        *(float2*)(out + i1) = make_float2(oacc[nt][2] * inv1, oacc[nt][3] * inv1);
    }
}

// ---------------------------------------------------------------------------
extern "C" void kernel_launch(void* const* d_in, const int* in_sizes, int n_in,
                              void* d_out, int out_size)
{
    const float* X  = (const float*)d_in[0];
    const float* Wq = (const float*)d_in[1];
    const float* Wk = (const float*)d_in[2];
    const float* Wv = (const float*)d_in[3];
    float* out = (float*)d_out;

    cudaFuncSetAttribute(qkv_mma_kernel,
                         cudaFuncAttributeMaxDynamicSharedMemorySize, GEMM_SMEM);
    cudaFuncSetAttribute(attn_mma_kernel,
                         cudaFuncAttributeMaxDynamicSharedMemorySize, ATTN_SMEM);

    split_x_kernel<<<(MTOT * DMODEL) / (256 * 4), 256>>>(X);
    split_wt_kernel<<<dim3(32, 32, 3), dim3(32, 8)>>>(Wq, Wk, Wv);

    dim3 ggrid(DMODEL / 128, MTOT / 128, 3);   // 8 x 64 x 3
    qkv_mma_kernel<<<ggrid, 256, GEMM_SMEM>>>();

    dim3 agrid(SEQ / 64, NBH);                 // 32 x 64
    attn_mma_kernel<<<agrid, 128, ATTN_SMEM>>>(out);
}

// round 8
// speedup vs baseline: 2.5907x; 1.0312x over previous
#include <cuda_runtime.h>
#include <cuda_fp16.h>
#include <cstdint>
#include <math.h>

#define BATCH  4
#define SEQ    2048
#define DMODEL 1024
#define NHEADS 16
#define DHEAD  64
#define NBH    (BATCH * NHEADS)   // 64
#define MTOT   (BATCH * SEQ)      // 8192

// ---------------- scratch (static device arrays; allocation-free) ----------
// Q,K: [bh][s][d] (d contiguous), Q pre-scaled by 0.125. V: [bh][d][s].
__device__ __half g_Qhi[(size_t)NBH * SEQ * DHEAD];
__device__ __half g_Qlo[(size_t)NBH * SEQ * DHEAD];
__device__ __half g_Khi[(size_t)NBH * SEQ * DHEAD];
__device__ __half g_Klo[(size_t)NBH * SEQ * DHEAD];
__device__ __half g_Vhi[(size_t)NBH * DHEAD * SEQ];
__device__ __half g_Vlo[(size_t)NBH * DHEAD * SEQ];

__device__ __half g_Xhi[(size_t)MTOT * DMODEL];
__device__ __half g_Xlo[(size_t)MTOT * DMODEL];
__device__ __half g_WThi[(size_t)3 * DMODEL * DMODEL];  // [which][n][k]
__device__ __half g_WTlo[(size_t)3 * DMODEL * DMODEL];

// ---------------- helpers ---------------------------------------------------
__device__ __forceinline__ void cp16(uint32_t dst, const void* src) {
    asm volatile("cp.async.cg.shared.global [%0], [%1], 16;" :: "r"(dst), "l"(src));
}
#define CP_COMMIT() asm volatile("cp.async.commit_group;" ::: "memory")
#define CP_WAIT(n)  asm volatile("cp.async.wait_group %0;" :: "n"(n) : "memory")

__device__ __forceinline__ uint32_t smem_u32(const void* p) {
    uint32_t a;
    asm("{ .reg .u64 t; cvta.to.shared.u64 t, %1; cvt.u32.u64 %0, t; }" : "=r"(a) : "l"(p));
    return a;
}
__device__ __forceinline__ uint32_t ld32sh(const __half* p) {
    return *(const uint32_t*)p;
}
__device__ __forceinline__ void mma16816(float* c, const uint32_t* a, const uint32_t* b) {
    asm volatile("mma.sync.aligned.m16n8k16.row.col.f32.f16.f16.f32 "
                 "{%0,%1,%2,%3}, {%4,%5,%6,%7}, {%8,%9}, {%0,%1,%2,%3};"
                 : "+f"(c[0]), "+f"(c[1]), "+f"(c[2]), "+f"(c[3])
                 : "r"(a[0]), "r"(a[1]), "r"(a[2]), "r"(a[3]), "r"(b[0]), "r"(b[1]));
}
__device__ __forceinline__ void ldsm4(uint32_t* r, uint32_t addr) {
    asm volatile("ldmatrix.sync.aligned.m8n8.x4.shared.b16 {%0,%1,%2,%3}, [%4];"
                 : "=r"(r[0]), "=r"(r[1]), "=r"(r[2]), "=r"(r[3]) : "r"(addr));
}
__device__ __forceinline__ uint32_t pack2h(__half a, __half b) {
    __half2 t = __halves2half2(a, b);
    return *(uint32_t*)&t;
}

// fast exp on FMA pipe: e^x for x <= ~0. rel err ~1.2e-7.
__device__ __forceinline__ float fexp(float x) {
    float t = x * 1.4426950408889634f;
    t = fmaxf(t, -30.f);
    int n = __float2int_rn(t);
    float f = t - (float)n;
    float p =               1.5403530393381610e-4f;
    p = fmaf(p, f, 1.3333558146428443e-3f);
    p = fmaf(p, f, 9.6181291076284772e-3f);
    p = fmaf(p, f, 5.5504108664821580e-2f);
    p = fmaf(p, f, 2.4022650695910071e-1f);
    p = fmaf(p, f, 6.9314718055994531e-1f);
    p = fmaf(p, f, 1.0f);
    return p * __int_as_float((n + 127) << 23);
}

// ---------------- conversion kernels ---------------------------------------
__global__ void split_x_kernel(const float* __restrict__ X)
{
    size_t i = ((size_t)blockIdx.x * blockDim.x + threadIdx.x) * 4;
    float4 v = *(const float4*)(X + i);
    float f[4] = {v.x, v.y, v.z, v.w};
#pragma unroll
    for (int j = 0; j < 4; j++) {
        __half hi = __float2half_rn(f[j]);
        g_Xhi[i + j] = hi;
        g_Xlo[i + j] = __float2half_rn(f[j] - __half2float(hi));
    }
}

__global__ void split_wt_kernel(const float* __restrict__ Wq,
                                const float* __restrict__ Wk,
                                const float* __restrict__ Wv)
{
    __shared__ float t[32][33];
    const float* W = (blockIdx.z == 0) ? Wq : (blockIdx.z == 1) ? Wk : Wv;
    int tx = threadIdx.x, ty = threadIdx.y;
    int n = blockIdx.x * 32 + tx;
#pragma unroll
    for (int i = 0; i < 4; i++) {
        int k = blockIdx.y * 32 + ty + i * 8;
        t[ty + i * 8][tx] = W[(size_t)k * DMODEL + n];
    }
    __syncthreads();
    size_t base = (size_t)blockIdx.z * DMODEL * DMODEL;
#pragma unroll
    for (int i = 0; i < 4; i++) {
        int nn = blockIdx.x * 32 + ty + i * 8;
        int kk = blockIdx.y * 32 + tx;
        float f = t[tx][ty + i * 8];
        __half hi = __float2half_rn(f);
        g_WThi[base + (size_t)nn * DMODEL + kk] = hi;
        g_WTlo[base + (size_t)nn * DMODEL + kk] = __float2half_rn(f - __half2float(hi));
    }
}

// ---------------- mma.sync split-fp16 projection GEMM ----------------------
constexpr int GKC = 32;
constexpr int NCHUNK = DMODEL / GKC;       // 32
constexpr int SST = 40;
constexpr uint32_t AHI = 0;
constexpr uint32_t ALO = 128 * SST * 2;
constexpr uint32_t BHI = 2 * 128 * SST * 2;
constexpr uint32_t BLO = 3 * 128 * SST * 2;
constexpr uint32_t STAGE = 4 * 128 * SST * 2;      // 40960
constexpr uint32_t GEMM_SMEM = 2 * STAGE;          // 81920

__global__ __launch_bounds__(256, 2)
void qkv_mma_kernel()
{
    extern __shared__ uint8_t sm[];
    const uint32_t sb = smem_u32(sm);

    const int tid = threadIdx.x;
    const int lane = tid & 31;
    const int warp = tid >> 5;
    const int wy = warp >> 2;
    const int wx = warp & 3;
    const int gid = lane >> 2;
    const int tig = lane & 3;

    const int which = blockIdx.z;
    const int n0 = blockIdx.x * 128;
    const int m0 = blockIdx.y * 128;

    const __half* __restrict__ WThi = g_WThi + (size_t)which * DMODEL * DMODEL;
    const __half* __restrict__ WTlo = g_WTlo + (size_t)which * DMODEL * DMODEL;

    auto load_chunk = [&](int c, int s) {
        const uint32_t stage = sb + (uint32_t)s * STAGE;
        const int c0 = c * GKC;
#pragma unroll
        for (int it = 0; it < 2; it++) {
            int idx = tid + it * 256;
            int r = idx >> 2, kg = idx & 3;
            uint32_t doff = (uint32_t)(r * SST * 2 + kg * 16);
            size_t asrc = (size_t)(m0 + r) * DMODEL + c0 + kg * 8;
            size_t bsrc = (size_t)(n0 + r) * DMODEL + c0 + kg * 8;
            cp16(stage + AHI + doff, g_Xhi + asrc);
            cp16(stage + ALO + doff, g_Xlo + asrc);
            cp16(stage + BHI + doff, WThi + bsrc);
            cp16(stage + BLO + doff, WTlo + bsrc);
        }
    };

    float acc[4][4][4];
#pragma unroll
    for (int mt = 0; mt < 4; mt++)
#pragma unroll
        for (int nt = 0; nt < 4; nt++)
#pragma unroll
            for (int j = 0; j < 4; j++) acc[mt][nt][j] = 0.f;

    load_chunk(0, 0);
    CP_COMMIT();

    for (int c = 0; c < NCHUNK; c++) {
        const int s = c & 1;
        if (c + 1 < NCHUNK) {
            load_chunk(c + 1, s ^ 1);
            CP_COMMIT();
            CP_WAIT(1);
        } else {
            CP_WAIT(0);
        }
        __syncthreads();

        const __half* Ah = (const __half*)(sm + s * STAGE + AHI);
        const __half* Al = (const __half*)(sm + s * STAGE + ALO);
        const __half* Bh = (const __half*)(sm + s * STAGE + BHI);
        const __half* Bl = (const __half*)(sm + s * STAGE + BLO);

#pragma unroll
        for (int ks = 0; ks < 2; ks++) {
            const int kbase = ks * 16 + tig * 2;
            uint32_t bh[4][2], bl[4][2];
#pragma unroll
            for (int nt = 0; nt < 4; nt++) {
                int rb = (wx * 32 + nt * 8 + gid) * SST + kbase;
                bh[nt][0] = ld32sh(Bh + rb);
                bh[nt][1] = ld32sh(Bh + rb + 8);
                bl[nt][0] = ld32sh(Bl + rb);
                bl[nt][1] = ld32sh(Bl + rb + 8);
            }
#pragma unroll
            for (int mt = 0; mt < 4; mt++) {
                int ra = (wy * 64 + mt * 16 + gid) * SST + kbase;
                uint32_t ah[4], al[4];
                ah[0] = ld32sh(Ah + ra);
                ah[1] = ld32sh(Ah + ra + 8 * SST);
                ah[2] = ld32sh(Ah + ra + 8);
                ah[3] = ld32sh(Ah + ra + 8 * SST + 8);
                al[0] = ld32sh(Al + ra);
                al[1] = ld32sh(Al + ra + 8 * SST);
                al[2] = ld32sh(Al + ra + 8);
                al[3] = ld32sh(Al + ra + 8 * SST + 8);
#pragma unroll
                for (int nt = 0; nt < 4; nt++) {
                    mma16816(acc[mt][nt], ah, bh[nt]);
                    mma16816(acc[mt][nt], ah, bl[nt]);
                    mma16816(acc[mt][nt], al, bh[nt]);
                }
            }
        }
        __syncthreads();
    }

    // ---- epilogue: emit fp16 hi/lo in attention-ready layouts -------------
#pragma unroll
    for (int mt = 0; mt < 4; mt++) {
#pragma unroll
        for (int hr = 0; hr < 2; hr++) {
            const int m = m0 + wy * 64 + mt * 16 + gid + hr * 8;
            const int bbp = m >> 11;
            const int sIdx = m & 2047;
#pragma unroll
            for (int nt = 0; nt < 4; nt++) {
                const int n = n0 + wx * 32 + nt * 8 + tig * 2;
                const int h = n >> 6, d = n & 63;
                float v0 = acc[mt][nt][hr * 2 + 0];
                float v1 = acc[mt][nt][hr * 2 + 1];
                if (which == 0) { v0 *= 0.125f; v1 *= 0.125f; }   // fold 1/sqrt(Dh) into Q
                __half h0 = __float2half_rn(v0), h1 = __float2half_rn(v1);
                __half e0 = __float2half_rn(v0 - __half2float(h0));
                __half e1 = __float2half_rn(v1 - __half2float(h1));
                if (which < 2) {
                    __half* hip = (which == 0) ? g_Qhi : g_Khi;
                    __half* lop = (which == 0) ? g_Qlo : g_Klo;
                    size_t idx = ((size_t)(bbp * NHEADS + h) * SEQ + sIdx) * DHEAD + d;
                    *(__half2*)(hip + idx) = __halves2half2(h0, h1);
                    *(__half2*)(lop + idx) = __halves2half2(e0, e1);
                } else {
                    size_t idx = ((size_t)(bbp * NHEADS + h) * DHEAD + d) * SEQ + sIdx;
                    g_Vhi[idx] = h0; g_Vhi[idx + SEQ] = h1;
                    g_Vlo[idx] = e0; g_Vlo[idx + SEQ] = e1;
                }
            }
        }
    }
}

// ---------------------------------------------------------------------------
// Flash attention, mma.sync + ldmatrix; P and Q fragments in registers.
// CTA: 128 threads (4 warps), 64 query rows; 2 CTAs/SM.
// ---------------------------------------------------------------------------
constexpr int AST = 72;                       // smem row stride in halves
constexpr uint32_t QHI_O = 0;
constexpr uint32_t QLO_O = 9216;
constexpr uint32_t STG_O = 18432;
constexpr uint32_t STGSZ = 36864;             // KH/KL/VH/VL x 9216
constexpr uint32_t KH_O = 0, KL_O = 9216, VH_O = 18432, VL_O = 27648;
constexpr uint32_t ATTN_SMEM = STG_O + 2 * STGSZ;   // 92160

__global__ __launch_bounds__(128, 2)
void attn_mma_kernel(float* __restrict__ out)
{
    extern __shared__ uint8_t sm[];
    const uint32_t sb = smem_u32(sm);

    const int tid = threadIdx.x;
    const int lane = tid & 31;
    const int w = tid >> 5;                        // 0..3
    const int gid = lane >> 2;
    const int tig = lane & 3;
    const int bh = blockIdx.y;
    const int qt = (gridDim.x - 1) - blockIdx.x;   // heavy blocks first
    const int q0 = qt * 64;
    const int bb = bh >> 4, h = bh & 15;

    // ldmatrix per-lane offsets (bytes).
    // A-frag x4: M0 rows0-7/klo, M1 rows8-15/klo, M2 rows0-7/khi, M3 rows8-15/khi.
    // B-frag x4: M0 n0-7/klo, M1 n0-7/khi, M2 n8-15/klo, M3 n8-15/khi
    //   -> regs = [b_nt(0..1), b_nt+1(0..1)].
    const uint32_t a_off = ((uint32_t)((lane & 15) * AST) + ((uint32_t)(lane >> 4) << 3)) * 2;
    const uint32_t b_off = ((uint32_t)(((lane & 7) + ((lane >> 4) << 3)) * AST) + (uint32_t)(lane & 8)) * 2;

    // ---- Q tile load (hi+lo): 64 rows x 64 d -----------------------------
#pragma unroll
    for (int comp = 0; comp < 2; comp++) {
#pragma unroll
        for (int it = 0; it < 4; it++) {
            int idx = tid + it * 128;
            int r = idx >> 3, g = idx & 7;
            uint32_t dst = sb + (comp ? QLO_O : QHI_O) + (uint32_t)(r * 144 + g * 16);
            const __half* src = (comp ? g_Qlo : g_Qhi) +
                                ((size_t)bh * SEQ + q0 + r) * DHEAD + g * 8;
            cp16(dst, src);
        }
    }

    auto load_kv = [&](int kt, int s) {
        uint32_t stage = sb + STG_O + (uint32_t)s * STGSZ;
#pragma unroll
        for (int comp = 0; comp < 4; comp++) {
#pragma unroll
            for (int it = 0; it < 4; it++) {
                int idx = tid + it * 128;
                int r = idx >> 3, g = idx & 7;
                uint32_t dst = stage + (uint32_t)comp * 9216u + (uint32_t)(r * 144 + g * 16);
                const __half* src;
                if (comp == 0)      src = g_Khi + ((size_t)bh * SEQ + kt * 64 + r) * DHEAD + g * 8;
                else if (comp == 1) src = g_Klo + ((size_t)bh * SEQ + kt * 64 + r) * DHEAD + g * 8;
                else if (comp == 2) src = g_Vhi + ((size_t)bh * DHEAD + r) * SEQ + kt * 64 + g * 8;
                else                src = g_Vlo + ((size_t)bh * DHEAD + r) * SEQ + kt * 64 + g * 8;
                cp16(dst, src);
            }
        }
    };

    load_kv(0, 0);
    CP_COMMIT();
    CP_WAIT(0);
    __syncthreads();

    // ---- hoist Q fragments to registers (invariant across kt) -------------
    uint32_t qh[4][4], ql[4][4];
    {
        const uint32_t qbase = sb + (uint32_t)(w * 16 * AST) * 2 + a_off;
#pragma unroll
        for (int ks = 0; ks < 4; ks++) {
            ldsm4(qh[ks], qbase + QHI_O + ks * 32);
            ldsm4(ql[ks], qbase + QLO_O + ks * 32);
        }
    }

    float m0 = -1e30f, m1 = -1e30f, l0 = 0.f, l1 = 0.f;
    float oacc[8][4];
#pragma unroll
    for (int nt = 0; nt < 8; nt++)
#pragma unroll
        for (int j = 0; j < 4; j++) oacc[nt][j] = 0.f;

    const int ktmax = min(qt + 1, SEQ / 64 - 1);
    const int rowbase = w * 16 + gid;

    for (int kt = 0; kt <= ktmax; kt++) {
        const int s = kt & 1;
        if (kt) __syncthreads();                  // stage s^1 free for reuse
        if (kt < ktmax) {
            load_kv(kt + 1, s ^ 1);
            CP_COMMIT();
            CP_WAIT(1);
        } else {
            CP_WAIT(0);
        }
        __syncthreads();

        const uint32_t stg = sb + STG_O + (uint32_t)s * STGSZ;

        // ---- S = Q K^T (split fp16, fp32 acc, ldmatrix B) ----------------
        float sacc[8][4];
#pragma unroll
        for (int nt = 0; nt < 8; nt++)
#pragma unroll
            for (int j = 0; j < 4; j++) sacc[nt][j] = 0.f;

#pragma unroll
        for (int ks = 0; ks < 4; ks++) {
            const uint32_t kofs = (uint32_t)(ks * 32) + b_off;
#pragma unroll
            for (int np = 0; np < 4; np++) {
                uint32_t kh4[4], kl4[4];
                ldsm4(kh4, stg + KH_O + (uint32_t)(np * 16 * AST * 2) + kofs);
                ldsm4(kl4, stg + KL_O + (uint32_t)(np * 16 * AST * 2) + kofs);
                mma16816(sacc[2 * np],     qh[ks], kh4);
                mma16816(sacc[2 * np],     qh[ks], kl4);
                mma16816(sacc[2 * np],     ql[ks], kh4);
                mma16816(sacc[2 * np + 1], qh[ks], kh4 + 2);
                mma16816(sacc[2 * np + 1], qh[ks], kl4 + 2);
                mma16816(sacc[2 * np + 1], ql[ks], kh4 + 2);
            }
        }

        // ---- mask: valid iff k <= q+1 (only kt >= qt tiles clip) ---------
        if (kt >= qt) {
            const int qg0 = q0 + rowbase, qg1 = qg0 + 8;
#pragma unroll
            for (int nt = 0; nt < 8; nt++) {
                const int c0 = kt * 64 + nt * 8 + tig * 2;
                if (c0     > qg0 + 1) sacc[nt][0] = -1e30f;
                if (c0 + 1 > qg0 + 1) sacc[nt][1] = -1e30f;
                if (c0     > qg1 + 1) sacc[nt][2] = -1e30f;
                if (c0 + 1 > qg1 + 1) sacc[nt][3] = -1e30f;
            }
        }

        // ---- online softmax (poly exp on FMA pipe) -----------------------
        float r0 = -1e30f, r1 = -1e30f;
#pragma unroll
        for (int nt = 0; nt < 8; nt++) {
            r0 = fmaxf(r0, fmaxf(sacc[nt][0], sacc[nt][1]));
            r1 = fmaxf(r1, fmaxf(sacc[nt][2], sacc[nt][3]));
        }
        r0 = fmaxf(r0, __shfl_xor_sync(0xffffffffu, r0, 1));
        r0 = fmaxf(r0, __shfl_xor_sync(0xffffffffu, r0, 2));
        r1 = fmaxf(r1, __shfl_xor_sync(0xffffffffu, r1, 1));
        r1 = fmaxf(r1, __shfl_xor_sync(0xffffffffu, r1, 2));

        const float mn0 = fmaxf(m0, r0), mn1 = fmaxf(m1, r1);
        const float sc0 = fexp(m0 - mn0), sc1 = fexp(m1 - mn1);
        m0 = mn0; m1 = mn1;

        // exp + pack P directly into PV A-operand fragments (no smem).
        uint32_t pha[4][4], pla[4][4];
        float rs0 = 0.f, rs1 = 0.f;
#pragma unroll
        for (int nt = 0; nt < 8; nt++) {
            float p0 = fexp(sacc[nt][0] - mn0);
            float p1 = fexp(sacc[nt][1] - mn0);
            float p2 = fexp(sacc[nt][2] - mn1);
            float p3 = fexp(sacc[nt][3] - mn1);
            rs0 += p0 + p1;
            rs1 += p2 + p3;
            __half hp0 = __float2half_rn(p0), hp1 = __float2half_rn(p1);
            __half hp2 = __float2half_rn(p2), hp3 = __float2half_rn(p3);
            const int ks = nt >> 1, hi2 = (nt & 1) << 1;
            pha[ks][hi2 + 0] = pack2h(hp0, hp1);            // row g
            pha[ks][hi2 + 1] = pack2h(hp2, hp3);            // row g+8
            pla[ks][hi2 + 0] = pack2h(__float2half_rn(p0 - __half2float(hp0)),
                                      __float2half_rn(p1 - __half2float(hp1)));
            pla[ks][hi2 + 1] = pack2h(__float2half_rn(p2 - __half2float(hp2)),
                                      __float2half_rn(p3 - __half2float(hp3)));
        }

        rs0 += __shfl_xor_sync(0xffffffffu, rs0, 1);
        rs0 += __shfl_xor_sync(0xffffffffu, rs0, 2);
        rs1 += __shfl_xor_sync(0xffffffffu, rs1, 1);
        rs1 += __shfl_xor_sync(0xffffffffu, rs1, 2);
        l0 = l0 * sc0 + rs0;
        l1 = l1 * sc1 + rs1;
#pragma unroll
        for (int nt = 0; nt < 8; nt++) {
            oacc[nt][0] *= sc0; oacc[nt][1] *= sc0;
            oacc[nt][2] *= sc1; oacc[nt][3] *= sc1;
        }

        // ---- O += P V (split fp16, P from registers, ldmatrix V) ---------
#pragma unroll
        for (int ks = 0; ks < 4; ks++) {
            const uint32_t kofs = (uint32_t)(ks * 32) + b_off;
#pragma unroll
            for (int np = 0; np < 4; np++) {
                uint32_t vh4[4], vl4[4];
                ldsm4(vh4, stg + VH_O + (uint32_t)(np * 16 * AST * 2) + kofs);
                ldsm4(vl4, stg + VL_O + (uint32_t)(np * 16 * AST * 2) + kofs);
                mma16816(oacc[2 * np],     pha[ks], vh4);
                mma16816(oacc[2 * np],     pha[ks], vl4);
                mma16816(oacc[2 * np],     pla[ks], vh4);
                mma16816(oacc[2 * np + 1], pha[ks], vh4 + 2);
                mma16816(oacc[2 * np + 1], pha[ks], vl4 + 2);
                mma16816(oacc[2 * np + 1], pla[ks], vh4 + 2);
            }
        }
    }

    // ---- epilogue: out[b][s][h*64+d] --------------------------------------
    const float inv0 = 1.f / l0, inv1 = 1.f / l1;
    const int s0 = q0 + rowbase;
#pragma unroll
    for (int nt = 0; nt < 8; nt++) {
        const int d = h * DHEAD + nt * 8 + tig * 2;
        size_t i0 = ((size_t)(bb * SEQ + s0)) * DMODEL + d;
        size_t i1 = ((size_t)(bb * SEQ + s0 + 8)) * DMODEL + d;
        *(float2*)(out + i0) = make_float2(oacc[nt][0] * inv0, oacc[nt][1] * inv0);
        *(float2*)(out + i1) = make_float2(oacc[nt][2] * inv1, oacc[nt][3] * inv1);
    }
}

// ---------------------------------------------------------------------------
extern "C" void kernel_launch(void* const* d_in, const int* in_sizes, int n_in,
                              void* d_out, int out_size)
{
    const float* X  = (const float*)d_in[0];
    const float* Wq = (const float*)d_in[1];
    const float* Wk = (const float*)d_in[2];
    const float* Wv = (const float*)d_in[3];
    float* out = (float*)d_out;

    cudaFuncSetAttribute(qkv_mma_kernel,
                         cudaFuncAttributeMaxDynamicSharedMemorySize, GEMM_SMEM);
    cudaFuncSetAttribute(attn_mma_kernel,
                         cudaFuncAttributeMaxDynamicSharedMemorySize, ATTN_SMEM);

    split_x_kernel<<<(MTOT * DMODEL) / (256 * 4), 256>>>(X);
    split_wt_kernel<<<dim3(32, 32, 3), dim3(32, 8)>>>(Wq, Wk, Wv);

    dim3 ggrid(DMODEL / 128, MTOT / 128, 3);   // 8 x 64 x 3
    qkv_mma_kernel<<<ggrid, 256, GEMM_SMEM>>>();

    dim3 agrid(SEQ / 64, NBH);                 // 32 x 64
    attn_mma_kernel<<<agrid, 128, ATTN_SMEM>>>(out);
}

// round 9
// speedup vs baseline: 2.8009x; 1.0812x over previous
#include <cuda_runtime.h>
#include <cuda_fp16.h>
#include <cstdint>
#include <math.h>

#define BATCH  4
#define SEQ    2048
#define DMODEL 1024
#define NHEADS 16
#define DHEAD  64
#define NBH    (BATCH * NHEADS)   // 64
#define MTOT   (BATCH * SEQ)      // 8192

// ---------------- scratch (static device arrays; allocation-free) ----------
// Q,K: [bh][s][d] (d contiguous), Q pre-scaled by 0.125*log2(e). V: [bh][d][s].
__device__ __half g_Qhi[(size_t)NBH * SEQ * DHEAD];
__device__ __half g_Qlo[(size_t)NBH * SEQ * DHEAD];
__device__ __half g_Khi[(size_t)NBH * SEQ * DHEAD];
__device__ __half g_Klo[(size_t)NBH * SEQ * DHEAD];
__device__ __half g_Vhi[(size_t)NBH * DHEAD * SEQ];
__device__ __half g_Vlo[(size_t)NBH * DHEAD * SEQ];

__device__ __half g_Xhi[(size_t)MTOT * DMODEL];
__device__ __half g_Xlo[(size_t)MTOT * DMODEL];
__device__ __half g_WThi[(size_t)3 * DMODEL * DMODEL];  // [which][n][k]
__device__ __half g_WTlo[(size_t)3 * DMODEL * DMODEL];

// ---------------- helpers ---------------------------------------------------
__device__ __forceinline__ void cp16(uint32_t dst, const void* src) {
    asm volatile("cp.async.cg.shared.global [%0], [%1], 16;" :: "r"(dst), "l"(src));
}
#define CP_COMMIT() asm volatile("cp.async.commit_group;" ::: "memory")
#define CP_WAIT(n)  asm volatile("cp.async.wait_group %0;" :: "n"(n) : "memory")

__device__ __forceinline__ uint32_t smem_u32(const void* p) {
    uint32_t a;
    asm("{ .reg .u64 t; cvta.to.shared.u64 t, %1; cvt.u32.u64 %0, t; }" : "=r"(a) : "l"(p));
    return a;
}
__device__ __forceinline__ uint32_t ld32sh(const __half* p) {
    return *(const uint32_t*)p;
}
__device__ __forceinline__ void mma16816(float* c, const uint32_t* a, const uint32_t* b) {
    asm volatile("mma.sync.aligned.m16n8k16.row.col.f32.f16.f16.f32 "
                 "{%0,%1,%2,%3}, {%4,%5,%6,%7}, {%8,%9}, {%0,%1,%2,%3};"
                 : "+f"(c[0]), "+f"(c[1]), "+f"(c[2]), "+f"(c[3])
                 : "r"(a[0]), "r"(a[1]), "r"(a[2]), "r"(a[3]), "r"(b[0]), "r"(b[1]));
}
__device__ __forceinline__ void ldsm4(uint32_t* r, uint32_t addr) {
    asm volatile("ldmatrix.sync.aligned.m8n8.x4.shared.b16 {%0,%1,%2,%3}, [%4];"
                 : "=r"(r[0]), "=r"(r[1]), "=r"(r[2]), "=r"(r[3]) : "r"(addr));
}
__device__ __forceinline__ uint32_t pack2h(__half a, __half b) {
    __half2 t = __halves2half2(a, b);
    return *(uint32_t*)&t;
}
// MUFU exp2 (logits are pre-scaled to base-2 domain)
__device__ __forceinline__ float fex2(float x) {
    float r;
    asm("ex2.approx.f32 %0, %1;" : "=f"(r) : "f"(x));
    return r;
}

// ---------------- conversion kernels ---------------------------------------
__global__ void split_x_kernel(const float* __restrict__ X)
{
    size_t i = ((size_t)blockIdx.x * blockDim.x + threadIdx.x) * 4;
    float4 v = *(const float4*)(X + i);
    float f[4] = {v.x, v.y, v.z, v.w};
#pragma unroll
    for (int j = 0; j < 4; j++) {
        __half hi = __float2half_rn(f[j]);
        g_Xhi[i + j] = hi;
        g_Xlo[i + j] = __float2half_rn(f[j] - __half2float(hi));
    }
}

__global__ void split_wt_kernel(const float* __restrict__ Wq,
                                const float* __restrict__ Wk,
                                const float* __restrict__ Wv)
{
    __shared__ float t[32][33];
    const float* W = (blockIdx.z == 0) ? Wq : (blockIdx.z == 1) ? Wk : Wv;
    int tx = threadIdx.x, ty = threadIdx.y;
    int n = blockIdx.x * 32 + tx;
#pragma unroll
    for (int i = 0; i < 4; i++) {
        int k = blockIdx.y * 32 + ty + i * 8;
        t[ty + i * 8][tx] = W[(size_t)k * DMODEL + n];
    }
    __syncthreads();
    size_t base = (size_t)blockIdx.z * DMODEL * DMODEL;
#pragma unroll
    for (int i = 0; i < 4; i++) {
        int nn = blockIdx.x * 32 + ty + i * 8;
        int kk = blockIdx.y * 32 + tx;
        float f = t[tx][ty + i * 8];
        __half hi = __float2half_rn(f);
        g_WThi[base + (size_t)nn * DMODEL + kk] = hi;
        g_WTlo[base + (size_t)nn * DMODEL + kk] = __float2half_rn(f - __half2float(hi));
    }
}

// ---------------- mma.sync split-fp16 projection GEMM ----------------------
constexpr int GKC = 32;
constexpr int NCHUNK = DMODEL / GKC;       // 32
constexpr int SST = 40;
constexpr uint32_t AHI = 0;
constexpr uint32_t ALO = 128 * SST * 2;
constexpr uint32_t BHI = 2 * 128 * SST * 2;
constexpr uint32_t BLO = 3 * 128 * SST * 2;
constexpr uint32_t STAGE = 4 * 128 * SST * 2;      // 40960
constexpr uint32_t GEMM_SMEM = 2 * STAGE;          // 81920

__global__ __launch_bounds__(256, 2)
void qkv_mma_kernel()
{
    extern __shared__ uint8_t sm[];
    const uint32_t sb = smem_u32(sm);

    const int tid = threadIdx.x;
    const int lane = tid & 31;
    const int warp = tid >> 5;
    const int wy = warp >> 2;
    const int wx = warp & 3;
    const int gid = lane >> 2;
    const int tig = lane & 3;

    const int which = blockIdx.z;
    const int n0 = blockIdx.x * 128;
    const int m0 = blockIdx.y * 128;

    const __half* __restrict__ WThi = g_WThi + (size_t)which * DMODEL * DMODEL;
    const __half* __restrict__ WTlo = g_WTlo + (size_t)which * DMODEL * DMODEL;

    auto load_chunk = [&](int c, int s) {
        const uint32_t stage = sb + (uint32_t)s * STAGE;
        const int c0 = c * GKC;
#pragma unroll
        for (int it = 0; it < 2; it++) {
            int idx = tid + it * 256;
            int r = idx >> 2, kg = idx & 3;
            uint32_t doff = (uint32_t)(r * SST * 2 + kg * 16);
            size_t asrc = (size_t)(m0 + r) * DMODEL + c0 + kg * 8;
            size_t bsrc = (size_t)(n0 + r) * DMODEL + c0 + kg * 8;
            cp16(stage + AHI + doff, g_Xhi + asrc);
            cp16(stage + ALO + doff, g_Xlo + asrc);
            cp16(stage + BHI + doff, WThi + bsrc);
            cp16(stage + BLO + doff, WTlo + bsrc);
        }
    };

    float acc[4][4][4];
#pragma unroll
    for (int mt = 0; mt < 4; mt++)
#pragma unroll
        for (int nt = 0; nt < 4; nt++)
#pragma unroll
            for (int j = 0; j < 4; j++) acc[mt][nt][j] = 0.f;

    load_chunk(0, 0);
    CP_COMMIT();

    for (int c = 0; c < NCHUNK; c++) {
        const int s = c & 1;
        if (c + 1 < NCHUNK) {
            load_chunk(c + 1, s ^ 1);
            CP_COMMIT();
            CP_WAIT(1);
        } else {
            CP_WAIT(0);
        }
        __syncthreads();

        const __half* Ah = (const __half*)(sm + s * STAGE + AHI);
        const __half* Al = (const __half*)(sm + s * STAGE + ALO);
        const __half* Bh = (const __half*)(sm + s * STAGE + BHI);
        const __half* Bl = (const __half*)(sm + s * STAGE + BLO);

#pragma unroll
        for (int ks = 0; ks < 2; ks++) {
            const int kbase = ks * 16 + tig * 2;
            uint32_t bh[4][2], bl[4][2];
#pragma unroll
            for (int nt = 0; nt < 4; nt++) {
                int rb = (wx * 32 + nt * 8 + gid) * SST + kbase;
                bh[nt][0] = ld32sh(Bh + rb);
                bh[nt][1] = ld32sh(Bh + rb + 8);
                bl[nt][0] = ld32sh(Bl + rb);
                bl[nt][1] = ld32sh(Bl + rb + 8);
            }
#pragma unroll
            for (int mt = 0; mt < 4; mt++) {
                int ra = (wy * 64 + mt * 16 + gid) * SST + kbase;
                uint32_t ah[4], al[4];
                ah[0] = ld32sh(Ah + ra);
                ah[1] = ld32sh(Ah + ra + 8 * SST);
                ah[2] = ld32sh(Ah + ra + 8);
                ah[3] = ld32sh(Ah + ra + 8 * SST + 8);
                al[0] = ld32sh(Al + ra);
                al[1] = ld32sh(Al + ra + 8 * SST);
                al[2] = ld32sh(Al + ra + 8);
                al[3] = ld32sh(Al + ra + 8 * SST + 8);
#pragma unroll
                for (int nt = 0; nt < 4; nt++) {
                    mma16816(acc[mt][nt], ah, bh[nt]);
                    mma16816(acc[mt][nt], ah, bl[nt]);
                    mma16816(acc[mt][nt], al, bh[nt]);
                }
            }
        }
        __syncthreads();
    }

    // ---- epilogue: emit fp16 hi/lo in attention-ready layouts -------------
    // Q is pre-scaled by 0.125*log2(e) so attention logits are base-2.
    const float QSCALE = 0.18033688011112042f;
#pragma unroll
    for (int mt = 0; mt < 4; mt++) {
#pragma unroll
        for (int hr = 0; hr < 2; hr++) {
            const int m = m0 + wy * 64 + mt * 16 + gid + hr * 8;
            const int bbp = m >> 11;
            const int sIdx = m & 2047;
#pragma unroll
            for (int nt = 0; nt < 4; nt++) {
                const int n = n0 + wx * 32 + nt * 8 + tig * 2;
                const int h = n >> 6, d = n & 63;
                float v0 = acc[mt][nt][hr * 2 + 0];
                float v1 = acc[mt][nt][hr * 2 + 1];
                if (which == 0) { v0 *= QSCALE; v1 *= QSCALE; }
                __half h0 = __float2half_rn(v0), h1 = __float2half_rn(v1);
                __half e0 = __float2half_rn(v0 - __half2float(h0));
                __half e1 = __float2half_rn(v1 - __half2float(h1));
                if (which < 2) {
                    __half* hip = (which == 0) ? g_Qhi : g_Khi;
                    __half* lop = (which == 0) ? g_Qlo : g_Klo;
                    size_t idx = ((size_t)(bbp * NHEADS + h) * SEQ + sIdx) * DHEAD + d;
                    *(__half2*)(hip + idx) = __halves2half2(h0, h1);
                    *(__half2*)(lop + idx) = __halves2half2(e0, e1);
                } else {
                    size_t idx = ((size_t)(bbp * NHEADS + h) * DHEAD + d) * SEQ + sIdx;
                    g_Vhi[idx] = h0; g_Vhi[idx + SEQ] = h1;
                    g_Vlo[idx] = e0; g_Vlo[idx + SEQ] = e1;
                }
            }
        }
    }
}

// ---------------------------------------------------------------------------
// Flash attention, mma.sync + ldmatrix; P and Q fragments in registers.
// Softmax in base-2 via MUFU ex2. PV uses P-hi only (error budget analysis
// in round notes: adds ~1.5e-4, total ~2e-4 < 1e-3 gate).
// CTA: 128 threads (4 warps), 64 query rows; 2 CTAs/SM.
// ---------------------------------------------------------------------------
constexpr int AST = 72;                       // smem row stride in halves
constexpr uint32_t QHI_O = 0;
constexpr uint32_t QLO_O = 9216;
constexpr uint32_t STG_O = 18432;
constexpr uint32_t STGSZ = 36864;             // KH/KL/VH/VL x 9216
constexpr uint32_t KH_O = 0, KL_O = 9216, VH_O = 18432, VL_O = 27648;
constexpr uint32_t ATTN_SMEM = STG_O + 2 * STGSZ;   // 92160

__global__ __launch_bounds__(128, 2)
void attn_mma_kernel(float* __restrict__ out)
{
    extern __shared__ uint8_t sm[];
    const uint32_t sb = smem_u32(sm);

    const int tid = threadIdx.x;
    const int lane = tid & 31;
    const int w = tid >> 5;                        // 0..3
    const int gid = lane >> 2;
    const int tig = lane & 3;
    const int bh = blockIdx.y;
    const int qt = (gridDim.x - 1) - blockIdx.x;   // heavy blocks first
    const int q0 = qt * 64;
    const int bb = bh >> 4, h = bh & 15;

    const uint32_t a_off = ((uint32_t)((lane & 15) * AST) + ((uint32_t)(lane >> 4) << 3)) * 2;
    const uint32_t b_off = ((uint32_t)(((lane & 7) + ((lane >> 4) << 3)) * AST) + (uint32_t)(lane & 8)) * 2;

    // ---- Q tile load (hi+lo): 64 rows x 64 d -----------------------------
#pragma unroll
    for (int comp = 0; comp < 2; comp++) {
#pragma unroll
        for (int it = 0; it < 4; it++) {
            int idx = tid + it * 128;
            int r = idx >> 3, g = idx & 7;
            uint32_t dst = sb + (comp ? QLO_O : QHI_O) + (uint32_t)(r * 144 + g * 16);
            const __half* src = (comp ? g_Qlo : g_Qhi) +
                                ((size_t)bh * SEQ + q0 + r) * DHEAD + g * 8;
            cp16(dst, src);
        }
    }

    auto load_kv = [&](int kt, int s) {
        uint32_t stage = sb + STG_O + (uint32_t)s * STGSZ;
#pragma unroll
        for (int comp = 0; comp < 4; comp++) {
#pragma unroll
            for (int it = 0; it < 4; it++) {
                int idx = tid + it * 128;
                int r = idx >> 3, g = idx & 7;
                uint32_t dst = stage + (uint32_t)comp * 9216u + (uint32_t)(r * 144 + g * 16);
                const __half* src;
                if (comp == 0)      src = g_Khi + ((size_t)bh * SEQ + kt * 64 + r) * DHEAD + g * 8;
                else if (comp == 1) src = g_Klo + ((size_t)bh * SEQ + kt * 64 + r) * DHEAD + g * 8;
                else if (comp == 2) src = g_Vhi + ((size_t)bh * DHEAD + r) * SEQ + kt * 64 + g * 8;
                else                src = g_Vlo + ((size_t)bh * DHEAD + r) * SEQ + kt * 64 + g * 8;
                cp16(dst, src);
            }
        }
    };

    load_kv(0, 0);
    CP_COMMIT();
    CP_WAIT(0);
    __syncthreads();

    // ---- hoist Q fragments to registers (invariant across kt) -------------
    uint32_t qh[4][4], ql[4][4];
    {
        const uint32_t qbase = sb + (uint32_t)(w * 16 * AST) * 2 + a_off;
#pragma unroll
        for (int ks = 0; ks < 4; ks++) {
            ldsm4(qh[ks], qbase + QHI_O + ks * 32);
            ldsm4(ql[ks], qbase + QLO_O + ks * 32);
        }
    }

    float m0 = -1e30f, m1 = -1e30f, l0 = 0.f, l1 = 0.f;
    float oacc[8][4];
#pragma unroll
    for (int nt = 0; nt < 8; nt++)
#pragma unroll
        for (int j = 0; j < 4; j++) oacc[nt][j] = 0.f;

    const int ktmax = min(qt + 1, SEQ / 64 - 1);
    const int rowbase = w * 16 + gid;

    for (int kt = 0; kt <= ktmax; kt++) {
        const int s = kt & 1;
        if (kt) __syncthreads();
        if (kt < ktmax) {
            load_kv(kt + 1, s ^ 1);
            CP_COMMIT();
            CP_WAIT(1);
        } else {
            CP_WAIT(0);
        }
        __syncthreads();

        const uint32_t stg = sb + STG_O + (uint32_t)s * STGSZ;

        // ---- S = Q K^T (split fp16, fp32 acc, ldmatrix B) ----------------
        float sacc[8][4];
#pragma unroll
        for (int nt = 0; nt < 8; nt++)
#pragma unroll
            for (int j = 0; j < 4; j++) sacc[nt][j] = 0.f;

#pragma unroll
        for (int ks = 0; ks < 4; ks++) {
            const uint32_t kofs = (uint32_t)(ks * 32) + b_off;
#pragma unroll
            for (int np = 0; np < 4; np++) {
                uint32_t kh4[4], kl4[4];
                ldsm4(kh4, stg + KH_O + (uint32_t)(np * 16 * AST * 2) + kofs);
                ldsm4(kl4, stg + KL_O + (uint32_t)(np * 16 * AST * 2) + kofs);
                mma16816(sacc[2 * np],     qh[ks], kh4);
                mma16816(sacc[2 * np],     qh[ks], kl4);
                mma16816(sacc[2 * np],     ql[ks], kh4);
                mma16816(sacc[2 * np + 1], qh[ks], kh4 + 2);
                mma16816(sacc[2 * np + 1], qh[ks], kl4 + 2);
                mma16816(sacc[2 * np + 1], ql[ks], kh4 + 2);
            }
        }

        // ---- mask: valid iff k <= q+1 (only kt >= qt tiles clip) ---------
        if (kt >= qt) {
            const int qg0 = q0 + rowbase, qg1 = qg0 + 8;
#pragma unroll
            for (int nt = 0; nt < 8; nt++) {
                const int c0 = kt * 64 + nt * 8 + tig * 2;
                if (c0     > qg0 + 1) sacc[nt][0] = -1e30f;
                if (c0 + 1 > qg0 + 1) sacc[nt][1] = -1e30f;
                if (c0     > qg1 + 1) sacc[nt][2] = -1e30f;
                if (c0 + 1 > qg1 + 1) sacc[nt][3] = -1e30f;
            }
        }

        // ---- online softmax, base-2 (MUFU ex2) ---------------------------
        float r0 = -1e30f, r1 = -1e30f;
#pragma unroll
        for (int nt = 0; nt < 8; nt++) {
            r0 = fmaxf(r0, fmaxf(sacc[nt][0], sacc[nt][1]));
            r1 = fmaxf(r1, fmaxf(sacc[nt][2], sacc[nt][3]));
        }
        r0 = fmaxf(r0, __shfl_xor_sync(0xffffffffu, r0, 1));
        r0 = fmaxf(r0, __shfl_xor_sync(0xffffffffu, r0, 2));
        r1 = fmaxf(r1, __shfl_xor_sync(0xffffffffu, r1, 1));
        r1 = fmaxf(r1, __shfl_xor_sync(0xffffffffu, r1, 2));

        const float mn0 = fmaxf(m0, r0), mn1 = fmaxf(m1, r1);
        const float sc0 = fex2(m0 - mn0), sc1 = fex2(m1 - mn1);
        m0 = mn0; m1 = mn1;

        // exp2 + pack P-hi directly into PV A-operand fragments
        uint32_t pha[4][4];
        float rs0 = 0.f, rs1 = 0.f;
#pragma unroll
        for (int nt = 0; nt < 8; nt++) {
            float p0 = fex2(sacc[nt][0] - mn0);
            float p1 = fex2(sacc[nt][1] - mn0);
            float p2 = fex2(sacc[nt][2] - mn1);
            float p3 = fex2(sacc[nt][3] - mn1);
            rs0 += p0 + p1;
            rs1 += p2 + p3;
            const int ks = nt >> 1, hi2 = (nt & 1) << 1;
            pha[ks][hi2 + 0] = pack2h(__float2half_rn(p0), __float2half_rn(p1));  // row g
            pha[ks][hi2 + 1] = pack2h(__float2half_rn(p2), __float2half_rn(p3));  // row g+8
        }

        rs0 += __shfl_xor_sync(0xffffffffu, rs0, 1);
        rs0 += __shfl_xor_sync(0xffffffffu, rs0, 2);
        rs1 += __shfl_xor_sync(0xffffffffu, rs1, 1);
        rs1 += __shfl_xor_sync(0xffffffffu, rs1, 2);
        l0 = l0 * sc0 + rs0;
        l1 = l1 * sc1 + rs1;
#pragma unroll
        for (int nt = 0; nt < 8; nt++) {
            oacc[nt][0] *= sc0; oacc[nt][1] *= sc0;
            oacc[nt][2] *= sc1; oacc[nt][3] *= sc1;
        }

        // ---- O += P V (P-hi x (V-hi + V-lo), ldmatrix V) -----------------
#pragma unroll
        for (int ks = 0; ks < 4; ks++) {
            const uint32_t kofs = (uint32_t)(ks * 32) + b_off;
#pragma unroll
            for (int np = 0; np < 4; np++) {
                uint32_t vh4[4], vl4[4];
                ldsm4(vh4, stg + VH_O + (uint32_t)(np * 16 * AST * 2) + kofs);
                ldsm4(vl4, stg + VL_O + (uint32_t)(np * 16 * AST * 2) + kofs);
                mma16816(oacc[2 * np],     pha[ks], vh4);
                mma16816(oacc[2 * np],     pha[ks], vl4);
                mma16816(oacc[2 * np + 1], pha[ks], vh4 + 2);
                mma16816(oacc[2 * np + 1], pha[ks], vl4 + 2);
            }
        }
    }

    // ---- epilogue: out[b][s][h*64+d] --------------------------------------
    const float inv0 = 1.f / l0, inv1 = 1.f / l1;
    const int s0 = q0 + rowbase;
#pragma unroll
    for (int nt = 0; nt < 8; nt++) {
        const int d = h * DHEAD + nt * 8 + tig * 2;
        size_t i0 = ((size_t)(bb * SEQ + s0)) * DMODEL + d;
        size_t i1 = ((size_t)(bb * SEQ + s0 + 8)) * DMODEL + d;
        *(float2*)(out + i0) = make_float2(oacc[nt][0] * inv0, oacc[nt][1] * inv0);
        *(float2*)(out + i1) = make_float2(oacc[nt][2] * inv1, oacc[nt][3] * inv1);
    }
}

// ---------------------------------------------------------------------------
extern "C" void kernel_launch(void* const* d_in, const int* in_sizes, int n_in,
                              void* d_out, int out_size)
{
    const float* X  = (const float*)d_in[0];
    const float* Wq = (const float*)d_in[1];
    const float* Wk = (const float*)d_in[2];
    const float* Wv = (const float*)d_in[3];
    float* out = (float*)d_out;

    cudaFuncSetAttribute(qkv_mma_kernel,
                         cudaFuncAttributeMaxDynamicSharedMemorySize, GEMM_SMEM);
    cudaFuncSetAttribute(attn_mma_kernel,
                         cudaFuncAttributeMaxDynamicSharedMemorySize, ATTN_SMEM);

    split_x_kernel<<<(MTOT * DMODEL) / (256 * 4), 256>>>(X);
    split_wt_kernel<<<dim3(32, 32, 3), dim3(32, 8)>>>(Wq, Wk, Wv);

    dim3 ggrid(DMODEL / 128, MTOT / 128, 3);   // 8 x 64 x 3
    qkv_mma_kernel<<<ggrid, 256, GEMM_SMEM>>>();

    dim3 agrid(SEQ / 64, NBH);                 // 32 x 64
    attn_mma_kernel<<<agrid, 128, ATTN_SMEM>>>(out);
}

// round 10
// speedup vs baseline: 2.9254x; 1.0444x over previous
#include <cuda_runtime.h>
#include <cuda_fp16.h>
#include <cstdint>
#include <math.h>

#define BATCH  4
#define SEQ    2048
#define DMODEL 1024
#define NHEADS 16
#define DHEAD  64
#define NBH    (BATCH * NHEADS)   // 64
#define MTOT   (BATCH * SEQ)      // 8192

// ---------------- scratch (static device arrays; allocation-free) ----------
// Q,K,V all [bh][s][d] (d contiguous). Q pre-scaled by 0.125*log2(e).
__device__ __half g_Qhi[(size_t)NBH * SEQ * DHEAD];
__device__ __half g_Qlo[(size_t)NBH * SEQ * DHEAD];
__device__ __half g_Khi[(size_t)NBH * SEQ * DHEAD];
__device__ __half g_Klo[(size_t)NBH * SEQ * DHEAD];
__device__ __half g_Vhi[(size_t)NBH * SEQ * DHEAD];
__device__ __half g_Vlo[(size_t)NBH * SEQ * DHEAD];

__device__ __half g_Xhi[(size_t)MTOT * DMODEL];
__device__ __half g_Xlo[(size_t)MTOT * DMODEL];
__device__ __half g_WThi[(size_t)3 * DMODEL * DMODEL];  // [which][n][k]
__device__ __half g_WTlo[(size_t)3 * DMODEL * DMODEL];

// ---------------- helpers ---------------------------------------------------
__device__ __forceinline__ void cp16(uint32_t dst, const void* src) {
    asm volatile("cp.async.cg.shared.global [%0], [%1], 16;" :: "r"(dst), "l"(src));
}
#define CP_COMMIT() asm volatile("cp.async.commit_group;" ::: "memory")
#define CP_WAIT(n)  asm volatile("cp.async.wait_group %0;" :: "n"(n) : "memory")

__device__ __forceinline__ uint32_t smem_u32(const void* p) {
    uint32_t a;
    asm("{ .reg .u64 t; cvta.to.shared.u64 t, %1; cvt.u32.u64 %0, t; }" : "=r"(a) : "l"(p));
    return a;
}
__device__ __forceinline__ void mma16816(float* c, const uint32_t* a, const uint32_t* b) {
    asm volatile("mma.sync.aligned.m16n8k16.row.col.f32.f16.f16.f32 "
                 "{%0,%1,%2,%3}, {%4,%5,%6,%7}, {%8,%9}, {%0,%1,%2,%3};"
                 : "+f"(c[0]), "+f"(c[1]), "+f"(c[2]), "+f"(c[3])
                 : "r"(a[0]), "r"(a[1]), "r"(a[2]), "r"(a[3]), "r"(b[0]), "r"(b[1]));
}
__device__ __forceinline__ void ldsm4(uint32_t* r, uint32_t addr) {
    asm volatile("ldmatrix.sync.aligned.m8n8.x4.shared.b16 {%0,%1,%2,%3}, [%4];"
                 : "=r"(r[0]), "=r"(r[1]), "=r"(r[2]), "=r"(r[3]) : "r"(addr));
}
__device__ __forceinline__ void ldsm4t(uint32_t* r, uint32_t addr) {
    asm volatile("ldmatrix.sync.aligned.m8n8.x4.trans.shared.b16 {%0,%1,%2,%3}, [%4];"
                 : "=r"(r[0]), "=r"(r[1]), "=r"(r[2]), "=r"(r[3]) : "r"(addr));
}
__device__ __forceinline__ uint32_t pack2h(__half a, __half b) {
    __half2 t = __halves2half2(a, b);
    return *(uint32_t*)&t;
}
// MUFU exp2 (logits are pre-scaled to base-2 domain)
__device__ __forceinline__ float fex2(float x) {
    float r;
    asm("ex2.approx.f32 %0, %1;" : "=f"(r) : "f"(x));
    return r;
}

// ---------------- conversion kernels ---------------------------------------
__global__ void split_x_kernel(const float* __restrict__ X)
{
    size_t i = ((size_t)blockIdx.x * blockDim.x + threadIdx.x) * 4;
    float4 v = *(const float4*)(X + i);
    float f[4] = {v.x, v.y, v.z, v.w};
#pragma unroll
    for (int j = 0; j < 4; j++) {
        __half hi = __float2half_rn(f[j]);
        g_Xhi[i + j] = hi;
        g_Xlo[i + j] = __float2half_rn(f[j] - __half2float(hi));
    }
}

__global__ void split_wt_kernel(const float* __restrict__ Wq,
                                const float* __restrict__ Wk,
                                const float* __restrict__ Wv)
{
    __shared__ float t[32][33];
    const float* W = (blockIdx.z == 0) ? Wq : (blockIdx.z == 1) ? Wk : Wv;
    int tx = threadIdx.x, ty = threadIdx.y;
    int n = blockIdx.x * 32 + tx;
#pragma unroll
    for (int i = 0; i < 4; i++) {
        int k = blockIdx.y * 32 + ty + i * 8;
        t[ty + i * 8][tx] = W[(size_t)k * DMODEL + n];
    }
    __syncthreads();
    size_t base = (size_t)blockIdx.z * DMODEL * DMODEL;
#pragma unroll
    for (int i = 0; i < 4; i++) {
        int nn = blockIdx.x * 32 + ty + i * 8;
        int kk = blockIdx.y * 32 + tx;
        float f = t[tx][ty + i * 8];
        __half hi = __float2half_rn(f);
        g_WThi[base + (size_t)nn * DMODEL + kk] = hi;
        g_WTlo[base + (size_t)nn * DMODEL + kk] = __float2half_rn(f - __half2float(hi));
    }
}

// ---------------- mma.sync split-fp16 projection GEMM ----------------------
constexpr int GKC = 32;
constexpr int NCHUNK = DMODEL / GKC;       // 32
constexpr int SST = 40;
constexpr uint32_t AHI = 0;
constexpr uint32_t ALO = 128 * SST * 2;
constexpr uint32_t BHI = 2 * 128 * SST * 2;
constexpr uint32_t BLO = 3 * 128 * SST * 2;
constexpr uint32_t STAGE = 4 * 128 * SST * 2;      // 40960
constexpr uint32_t GEMM_SMEM = 2 * STAGE;          // 81920

__global__ __launch_bounds__(256, 2)
void qkv_mma_kernel()
{
    extern __shared__ uint8_t sm[];
    const uint32_t sb = smem_u32(sm);

    const int tid = threadIdx.x;
    const int lane = tid & 31;
    const int warp = tid >> 5;
    const int wy = warp >> 2;
    const int wx = warp & 3;
    const int gid = lane >> 2;
    const int tig = lane & 3;

    const int which = blockIdx.z;
    const int n0 = blockIdx.x * 128;
    const int m0 = blockIdx.y * 128;

    const __half* __restrict__ WThi = g_WThi + (size_t)which * DMODEL * DMODEL;
    const __half* __restrict__ WTlo = g_WTlo + (size_t)which * DMODEL * DMODEL;

    // ldmatrix lane offsets (bytes); SST*2 = 80B row stride (16B-aligned, conflict-free)
    const uint32_t a_off = ((uint32_t)((lane & 15) * SST) + ((uint32_t)(lane >> 4) << 3)) * 2;
    const uint32_t b_off = ((uint32_t)(((lane & 7) + ((lane >> 4) << 3)) * SST) + (uint32_t)(lane & 8)) * 2;

    auto load_chunk = [&](int c, int s) {
        const uint32_t stage = sb + (uint32_t)s * STAGE;
        const int c0 = c * GKC;
#pragma unroll
        for (int it = 0; it < 2; it++) {
            int idx = tid + it * 256;
            int r = idx >> 2, kg = idx & 3;
            uint32_t doff = (uint32_t)(r * SST * 2 + kg * 16);
            size_t asrc = (size_t)(m0 + r) * DMODEL + c0 + kg * 8;
            size_t bsrc = (size_t)(n0 + r) * DMODEL + c0 + kg * 8;
            cp16(stage + AHI + doff, g_Xhi + asrc);
            cp16(stage + ALO + doff, g_Xlo + asrc);
            cp16(stage + BHI + doff, WThi + bsrc);
            cp16(stage + BLO + doff, WTlo + bsrc);
        }
    };

    float acc[4][4][4];
#pragma unroll
    for (int mt = 0; mt < 4; mt++)
#pragma unroll
        for (int nt = 0; nt < 4; nt++)
#pragma unroll
            for (int j = 0; j < 4; j++) acc[mt][nt][j] = 0.f;

    load_chunk(0, 0);
    CP_COMMIT();

    for (int c = 0; c < NCHUNK; c++) {
        const int s = c & 1;
        if (c + 1 < NCHUNK) {
            load_chunk(c + 1, s ^ 1);
            CP_COMMIT();
            CP_WAIT(1);
        } else {
            CP_WAIT(0);
        }
        __syncthreads();

        const uint32_t stg = sb + (uint32_t)s * STAGE;

#pragma unroll
        for (int ks = 0; ks < 2; ks++) {
            const uint32_t koff = (uint32_t)(ks * 32);
            uint32_t bh4[2][4], bl4[2][4];
#pragma unroll
            for (int np = 0; np < 2; np++) {
                const uint32_t brow = (uint32_t)((wx * 32 + np * 16) * SST * 2);
                ldsm4(bh4[np], stg + BHI + brow + koff + b_off);
                ldsm4(bl4[np], stg + BLO + brow + koff + b_off);
            }
#pragma unroll
            for (int mt = 0; mt < 4; mt++) {
                const uint32_t arow = (uint32_t)((wy * 64 + mt * 16) * SST * 2);
                uint32_t ah[4], al[4];
                ldsm4(ah, stg + AHI + arow + koff + a_off);
                ldsm4(al, stg + ALO + arow + koff + a_off);
#pragma unroll
                for (int np = 0; np < 2; np++) {
                    mma16816(acc[mt][2 * np],     ah, bh4[np]);
                    mma16816(acc[mt][2 * np],     ah, bl4[np]);
                    mma16816(acc[mt][2 * np],     al, bh4[np]);
                    mma16816(acc[mt][2 * np + 1], ah, bh4[np] + 2);
                    mma16816(acc[mt][2 * np + 1], ah, bl4[np] + 2);
                    mma16816(acc[mt][2 * np + 1], al, bh4[np] + 2);
                }
            }
        }
        __syncthreads();
    }

    // ---- epilogue: emit fp16 hi/lo, all [bh][s][d] ------------------------
    // Q is pre-scaled by 0.125*log2(e) so attention logits are base-2.
    const float QSCALE = 0.18033688011112042f;
#pragma unroll
    for (int mt = 0; mt < 4; mt++) {
#pragma unroll
        for (int hr = 0; hr < 2; hr++) {
            const int m = m0 + wy * 64 + mt * 16 + gid + hr * 8;
            const int bbp = m >> 11;
            const int sIdx = m & 2047;
#pragma unroll
            for (int nt = 0; nt < 4; nt++) {
                const int n = n0 + wx * 32 + nt * 8 + tig * 2;
                const int h = n >> 6, d = n & 63;
                float v0 = acc[mt][nt][hr * 2 + 0];
                float v1 = acc[mt][nt][hr * 2 + 1];
                if (which == 0) { v0 *= QSCALE; v1 *= QSCALE; }
                __half h0 = __float2half_rn(v0), h1 = __float2half_rn(v1);
                __half e0 = __float2half_rn(v0 - __half2float(h0));
                __half e1 = __float2half_rn(v1 - __half2float(h1));
                __half* hip = (which == 0) ? g_Qhi : (which == 1) ? g_Khi : g_Vhi;
                __half* lop = (which == 0) ? g_Qlo : (which == 1) ? g_Klo : g_Vlo;
                size_t idx = ((size_t)(bbp * NHEADS + h) * SEQ + sIdx) * DHEAD + d;
                *(__half2*)(hip + idx) = __halves2half2(h0, h1);
                *(__half2*)(lop + idx) = __halves2half2(e0, e1);
            }
        }
    }
}

// ---------------------------------------------------------------------------
// Flash attention, mma.sync + ldmatrix; P and Q fragments in registers.
// V loaded row-major [s][d] and fed to PV via ldmatrix.trans (FA2 pattern).
// Softmax in base-2 via MUFU ex2; PV uses P-hi only.
// CTA: 128 threads (4 warps), 64 query rows; 2 CTAs/SM.
// ---------------------------------------------------------------------------
constexpr int AST = 72;                       // smem row stride in halves
constexpr uint32_t QHI_O = 0;
constexpr uint32_t QLO_O = 9216;
constexpr uint32_t STG_O = 18432;
constexpr uint32_t STGSZ = 36864;             // KH/KL/VH/VL x 9216
constexpr uint32_t KH_O = 0, KL_O = 9216, VH_O = 18432, VL_O = 27648;
constexpr uint32_t ATTN_SMEM = STG_O + 2 * STGSZ;   // 92160

__global__ __launch_bounds__(128, 2)
void attn_mma_kernel(float* __restrict__ out)
{
    extern __shared__ uint8_t sm[];
    const uint32_t sb = smem_u32(sm);

    const int tid = threadIdx.x;
    const int lane = tid & 31;
    const int w = tid >> 5;                        // 0..3
    const int gid = lane >> 2;
    const int tig = lane & 3;
    const int bh = blockIdx.y;
    const int qt = (gridDim.x - 1) - blockIdx.x;   // heavy blocks first
    const int q0 = qt * 64;
    const int bb = bh >> 4, h = bh & 15;

    const uint32_t a_off = ((uint32_t)((lane & 15) * AST) + ((uint32_t)(lane >> 4) << 3)) * 2;
    const uint32_t b_off = ((uint32_t)(((lane & 7) + ((lane >> 4) << 3)) * AST) + (uint32_t)(lane & 8)) * 2;
    // trans-ldmatrix offsets for V [s][d]: rows = s, cols = d
    const uint32_t v_off = ((uint32_t)(((lane & 7) + ((lane >> 3) & 1) * 8) * AST) + ((uint32_t)(lane >> 4) << 3)) * 2;

    // ---- Q tile load (hi+lo): 64 rows x 64 d -----------------------------
#pragma unroll
    for (int comp = 0; comp < 2; comp++) {
#pragma unroll
        for (int it = 0; it < 4; it++) {
            int idx = tid + it * 128;
            int r = idx >> 3, g = idx & 7;
            uint32_t dst = sb + (comp ? QLO_O : QHI_O) + (uint32_t)(r * 144 + g * 16);
            const __half* src = (comp ? g_Qlo : g_Qhi) +
                                ((size_t)bh * SEQ + q0 + r) * DHEAD + g * 8;
            cp16(dst, src);
        }
    }

    auto load_kv = [&](int kt, int s) {
        uint32_t stage = sb + STG_O + (uint32_t)s * STGSZ;
        const __half* bases[4] = { g_Khi, g_Klo, g_Vhi, g_Vlo };
#pragma unroll
        for (int comp = 0; comp < 4; comp++) {
#pragma unroll
            for (int it = 0; it < 4; it++) {
                int idx = tid + it * 128;
                int r = idx >> 3, g = idx & 7;
                uint32_t dst = stage + (uint32_t)comp * 9216u + (uint32_t)(r * 144 + g * 16);
                const __half* src = bases[comp] +
                                    ((size_t)bh * SEQ + kt * 64 + r) * DHEAD + g * 8;
                cp16(dst, src);
            }
        }
    };

    load_kv(0, 0);
    CP_COMMIT();
    CP_WAIT(0);
    __syncthreads();

    // ---- hoist Q fragments to registers (invariant across kt) -------------
    uint32_t qh[4][4], ql[4][4];
    {
        const uint32_t qbase = sb + (uint32_t)(w * 16 * AST) * 2 + a_off;
#pragma unroll
        for (int ks = 0; ks < 4; ks++) {
            ldsm4(qh[ks], qbase + QHI_O + ks * 32);
            ldsm4(ql[ks], qbase + QLO_O + ks * 32);
        }
    }

    float m0 = -1e30f, m1 = -1e30f, l0 = 0.f, l1 = 0.f;
    float oacc[8][4];
#pragma unroll
    for (int nt = 0; nt < 8; nt++)
#pragma unroll
        for (int j = 0; j < 4; j++) oacc[nt][j] = 0.f;

    const int ktmax = min(qt + 1, SEQ / 64 - 1);
    const int rowbase = w * 16 + gid;

    for (int kt = 0; kt <= ktmax; kt++) {
        const int s = kt & 1;
        if (kt) __syncthreads();
        if (kt < ktmax) {
            load_kv(kt + 1, s ^ 1);
            CP_COMMIT();
            CP_WAIT(1);
        } else {
            CP_WAIT(0);
        }
        __syncthreads();

        const uint32_t stg = sb + STG_O + (uint32_t)s * STGSZ;

        // ---- S = Q K^T (split fp16, fp32 acc, ldmatrix B) ----------------
        float sacc[8][4];
#pragma unroll
        for (int nt = 0; nt < 8; nt++)
#pragma unroll
            for (int j = 0; j < 4; j++) sacc[nt][j] = 0.f;

#pragma unroll
        for (int ks = 0; ks < 4; ks++) {
            const uint32_t kofs = (uint32_t)(ks * 32) + b_off;
#pragma unroll
            for (int np = 0; np < 4; np++) {
                uint32_t kh4[4], kl4[4];
                ldsm4(kh4, stg + KH_O + (uint32_t)(np * 16 * AST * 2) + kofs);
                ldsm4(kl4, stg + KL_O + (uint32_t)(np * 16 * AST * 2) + kofs);
                mma16816(sacc[2 * np],     qh[ks], kh4);
                mma16816(sacc[2 * np],     qh[ks], kl4);
                mma16816(sacc[2 * np],     ql[ks], kh4);
                mma16816(sacc[2 * np + 1], qh[ks], kh4 + 2);
                mma16816(sacc[2 * np + 1], qh[ks], kl4 + 2);
                mma16816(sacc[2 * np + 1], ql[ks], kh4 + 2);
            }
        }

        // ---- mask: valid iff k <= q+1 (only kt >= qt tiles clip) ---------
        if (kt >= qt) {
            const int qg0 = q0 + rowbase, qg1 = qg0 + 8;
#pragma unroll
            for (int nt = 0; nt < 8; nt++) {
                const int c0 = kt * 64 + nt * 8 + tig * 2;
                if (c0     > qg0 + 1) sacc[nt][0] = -1e30f;
                if (c0 + 1 > qg0 + 1) sacc[nt][1] = -1e30f;
                if (c0     > qg1 + 1) sacc[nt][2] = -1e30f;
                if (c0 + 1 > qg1 + 1) sacc[nt][3] = -1e30f;
            }
        }

        // ---- online softmax, base-2 (MUFU ex2) ---------------------------
        float r0 = -1e30f, r1 = -1e30f;
#pragma unroll
        for (int nt = 0; nt < 8; nt++) {
            r0 = fmaxf(r0, fmaxf(sacc[nt][0], sacc[nt][1]));
            r1 = fmaxf(r1, fmaxf(sacc[nt][2], sacc[nt][3]));
        }
        r0 = fmaxf(r0, __shfl_xor_sync(0xffffffffu, r0, 1));
        r0 = fmaxf(r0, __shfl_xor_sync(0xffffffffu, r0, 2));
        r1 = fmaxf(r1, __shfl_xor_sync(0xffffffffu, r1, 1));
        r1 = fmaxf(r1, __shfl_xor_sync(0xffffffffu, r1, 2));

        const float mn0 = fmaxf(m0, r0), mn1 = fmaxf(m1, r1);
        const float sc0 = fex2(m0 - mn0), sc1 = fex2(m1 - mn1);
        m0 = mn0; m1 = mn1;

        // exp2 + pack P-hi directly into PV A-operand fragments
        uint32_t pha[4][4];
        float rs0 = 0.f, rs1 = 0.f;
#pragma unroll
        for (int nt = 0; nt < 8; nt++) {
            float p0 = fex2(sacc[nt][0] - mn0);
            float p1 = fex2(sacc[nt][1] - mn0);
            float p2 = fex2(sacc[nt][2] - mn1);
            float p3 = fex2(sacc[nt][3] - mn1);
            rs0 += p0 + p1;
            rs1 += p2 + p3;
            const int ks = nt >> 1, hi2 = (nt & 1) << 1;
            pha[ks][hi2 + 0] = pack2h(__float2half_rn(p0), __float2half_rn(p1));  // row g
            pha[ks][hi2 + 1] = pack2h(__float2half_rn(p2), __float2half_rn(p3));  // row g+8
        }

        rs0 += __shfl_xor_sync(0xffffffffu, rs0, 1);
        rs0 += __shfl_xor_sync(0xffffffffu, rs0, 2);
        rs1 += __shfl_xor_sync(0xffffffffu, rs1, 1);
        rs1 += __shfl_xor_sync(0xffffffffu, rs1, 2);
        l0 = l0 * sc0 + rs0;
        l1 = l1 * sc1 + rs1;
#pragma unroll
        for (int nt = 0; nt < 8; nt++) {
            oacc[nt][0] *= sc0; oacc[nt][1] *= sc0;
            oacc[nt][2] *= sc1; oacc[nt][3] *= sc1;
        }

        // ---- O += P V (P-hi x (V-hi + V-lo), trans-ldmatrix V) -----------
#pragma unroll
        for (int ks = 0; ks < 4; ks++) {
            const uint32_t srow = (uint32_t)(ks * 16 * AST * 2) + v_off;
#pragma unroll
            for (int np = 0; np < 4; np++) {
                uint32_t vh4[4], vl4[4];
                ldsm4t(vh4, stg + VH_O + srow + (uint32_t)(np * 32));
                ldsm4t(vl4, stg + VL_O + srow + (uint32_t)(np * 32));
                mma16816(oacc[2 * np],     pha[ks], vh4);
                mma16816(oacc[2 * np],     pha[ks], vl4);
                mma16816(oacc[2 * np + 1], pha[ks], vh4 + 2);
                mma16816(oacc[2 * np + 1], pha[ks], vl4 + 2);
            }
        }
    }

    // ---- epilogue: out[b][s][h*64+d] --------------------------------------
    const float inv0 = 1.f / l0, inv1 = 1.f / l1;
    const int s0 = q0 + rowbase;
#pragma unroll
    for (int nt = 0; nt < 8; nt++) {
        const int d = h * DHEAD + nt * 8 + tig * 2;
        size_t i0 = ((size_t)(bb * SEQ + s0)) * DMODEL + d;
        size_t i1 = ((size_t)(bb * SEQ + s0 + 8)) * DMODEL + d;
        *(float2*)(out + i0) = make_float2(oacc[nt][0] * inv0, oacc[nt][1] * inv0);
        *(float2*)(out + i1) = make_float2(oacc[nt][2] * inv1, oacc[nt][3] * inv1);
    }
}

// ---------------------------------------------------------------------------
extern "C" void kernel_launch(void* const* d_in, const int* in_sizes, int n_in,
                              void* d_out, int out_size)
{
    const float* X  = (const float*)d_in[0];
    const float* Wq = (const float*)d_in[1];
    const float* Wk = (const float*)d_in[2];
    const float* Wv = (const float*)d_in[3];
    float* out = (float*)d_out;

    cudaFuncSetAttribute(qkv_mma_kernel,
                         cudaFuncAttributeMaxDynamicSharedMemorySize, GEMM_SMEM);
    cudaFuncSetAttribute(attn_mma_kernel,
                         cudaFuncAttributeMaxDynamicSharedMemorySize, ATTN_SMEM);

    split_x_kernel<<<(MTOT * DMODEL) / (256 * 4), 256>>>(X);
    split_wt_kernel<<<dim3(32, 32, 3), dim3(32, 8)>>>(Wq, Wk, Wv);

    dim3 ggrid(DMODEL / 128, MTOT / 128, 3);   // 8 x 64 x 3
    qkv_mma_kernel<<<ggrid, 256, GEMM_SMEM>>>();

    dim3 agrid(SEQ / 64, NBH);                 // 32 x 64
    attn_mma_kernel<<<agrid, 128, ATTN_SMEM>>>(out);
}